// round 14
// baseline (speedup 1.0000x reference)
#include <cuda_runtime.h>
#include <cuda_fp16.h>
#include <mma.h>
#include <math.h>

using namespace nvcuda;

#define NT 50000
#define NTP 50048    // NT padded to 128 for wmma row tiles
#define NP 256
#define NE 800000
#define EMB 64
#define H 4
#define HE 256       // H*EMB
#define NL 3
#define EDIM 8
#define TDIM 16
#define PDIM 8
#define NG 8
#define SCAN_B 196   // ceil(NT/256)
#define WCAP 64      // per-warp smem edge stash (deg <= 64 fast path)

// ---------------- scratch (static __device__, no allocs) ----------------
// state-recycling invariant: g_deg, g_meanea, g_tp, g_cntt, g_barcnt, g_donecnt
// are zero at entry (zero-init at load; reset by their consumers every run).
// g_gout rows [NT, NTP) stay zero forever (never written) -> safe wmma loads.
__device__ __half  g_xlh[(size_t)NT * HE];      // fp16 transformed feats (only copy)
__device__ __half  g_gout[(size_t)NTP * HE];    // fp16 GAT aggregation output (padded)
__device__ float   g_ht[(size_t)NT * EMB];
__device__ float   g_hp[NP * EMB];
__device__ float   g_asrc[NT * H];
__device__ float   g_adst[NT * H];
__device__ float   g_exbuf[(size_t)NE * H];     // overflow (deg > WCAP) ex only
__device__ float   g_aedg[(size_t)NL * NE * H]; // per-edge per-layer attention dots (CSR order)
__device__ int     g_permsrc[NE];
__device__ int     g_rowptr[NT + 1];
__device__ int     g_deg[NT];
__device__ int     g_off[NT];
__device__ int     g_bsum[SCAN_B];
__device__ float   g_meanea[EDIM];
__device__ float   g_c[NL * EDIM * H];
__device__ float   g_loopae[NL * H];
__device__ float   g_tp[NG * EMB];
__device__ int     g_cntt[NG];
__device__ int     g_barcnt;
__device__ int     g_donecnt;

// ---------------- fused setup: task embed + proc embed + meanea + dst hist ----------
__global__ void k_setup(const float* __restrict__ xt, const float* __restrict__ Wt,
                        const float* __restrict__ bt, const float* __restrict__ xp,
                        const float* __restrict__ Wp, const float* __restrict__ bp,
                        const float* __restrict__ ea, const int* __restrict__ dst) {
    int b = blockIdx.x;
    int tid = threadIdx.x;
    if (b < NT / 4) {
        __shared__ float sW[TDIM * EMB];
        __shared__ float sb[EMB];
        __shared__ float sx[4][TDIM];
        int tx = tid & 63, ty = tid >> 6;
        for (int i = tid; i < TDIM * EMB; i += 256) sW[i] = Wt[i];
        if (tid < EMB) sb[tid] = bt[tid];
        int n = b * 4 + ty;
        if (tx < TDIM) sx[ty][tx] = xt[(size_t)n * TDIM + tx];
        __syncthreads();
        float a = sb[tx];
#pragma unroll
        for (int k = 0; k < TDIM; k++) a = fmaf(sx[ty][k], sW[k * EMB + tx], a);
        g_ht[(size_t)n * EMB + tx] = a;
    } else if (b < NT / 4 + 64) {
        int idx = (b - NT / 4) * 256 + tid;
        int n = idx >> 6, c = idx & 63;
        float a = bp[c];
#pragma unroll
        for (int k = 0; k < PDIM; k++)
            a = fmaf(__ldg(&xp[n * PDIM + k]), __ldg(&Wp[k * EMB + c]), a);
        g_hp[idx] = a;
    } else {
        int i = (b - NT / 4 - 64) * 256 + tid;
        int stride = 512 * 256;
        float acc[8] = {0, 0, 0, 0, 0, 0, 0, 0};
        for (int e = i; e < NE; e += stride) {
            const float4* p = (const float4*)(ea + (size_t)e * 8);
            float4 a0 = p[0], a1 = p[1];
            acc[0] += a0.x; acc[1] += a0.y; acc[2] += a0.z; acc[3] += a0.w;
            acc[4] += a1.x; acc[5] += a1.y; acc[6] += a1.z; acc[7] += a1.w;
            atomicAdd(&g_deg[dst[e]], 1);
        }
#pragma unroll
        for (int k = 0; k < 8; k++)
#pragma unroll
            for (int off = 16; off >= 1; off >>= 1)
                acc[k] += __shfl_xor_sync(0xffffffffu, acc[k], off);
        if ((tid & 31) == 0)
#pragma unroll
            for (int k = 0; k < 8; k++) atomicAdd(&g_meanea[k], acc[k]);
    }
}

// ---------------- grid barrier (all 196 blocks co-resident; self-resetting) --------
__device__ __forceinline__ void gbar(int target) {
    __syncthreads();
    if (threadIdx.x == 0) {
        __threadfence();
        atomicAdd(&g_barcnt, 1);
        while (atomicAdd(&g_barcnt, 0) < target) { }
        __threadfence();
    }
    __syncthreads();
}

// ---------------- CSR build: scan + cvec + scatter(+aedg all layers) in ONE kernel ----
__global__ void k_csr(const int* __restrict__ src, const int* __restrict__ dst,
                      const float* __restrict__ ea, const float* __restrict__ We,
                      const float* __restrict__ ae) {
    int b = blockIdx.x, t = threadIdx.x;
    __shared__ int sm[256];
    __shared__ float scc[NL * 32];
    int idx = b * 256 + t;
    int v = (idx < NT) ? g_deg[idx] : 0;
    sm[t] = v;
    __syncthreads();
    for (int off = 1; off < 256; off <<= 1) {
        int u = (t >= off) ? sm[t - off] : 0;
        __syncthreads();
        sm[t] += u;
        __syncthreads();
    }
    if (idx < NT) g_rowptr[idx] = sm[t] - v;
    if (t == 255) g_bsum[b] = sm[255];
    gbar(SCAN_B);
    if (b == 0) {
        int w = (t < SCAN_B) ? g_bsum[t] : 0;
        sm[t] = w;
        __syncthreads();
        for (int off = 1; off < 256; off <<= 1) {
            int u = (t >= off) ? sm[t - off] : 0;
            __syncthreads();
            sm[t] += u;
            __syncthreads();
        }
        if (t < SCAN_B) g_bsum[t] = sm[t] - w;
    } else if (b == 1) {
        if (t < NL * EDIM * H) {
            int l = t >> 5; int r = t & 31; int j = r >> 2; int h = r & 3;
            float s = 0.f;
            for (int d = 0; d < EMB; d++)
                s += We[((size_t)(l * EDIM + j)) * HE + h * EMB + d] * ae[(l * H + h) * EMB + d];
            g_c[t] = s;
        }
        __syncthreads();
        if (t < NL * H) {
            int l = t >> 2; int h = t & 3;
            float s = 0.f;
            for (int j = 0; j < EDIM; j++)
                s += (g_meanea[j] * (1.f / NE)) * g_c[l * 32 + j * 4 + h];
            g_loopae[t] = s;
        }
        __syncthreads();
        if (t < EDIM) g_meanea[t] = 0.f;
    }
    gbar(2 * SCAN_B);
    if (idx < NT) {
        int r = g_rowptr[idx] + g_bsum[b];
        g_rowptr[idx] = r;
        g_off[idx] = r;
        g_deg[idx] = 0;
    }
    if (b == 0 && t == 0) g_rowptr[NT] = NE;
    gbar(3 * SCAN_B);
    if (t < NL * 32) scc[t] = g_c[t];
    __syncthreads();
    for (int e = b * 256 + t; e < NE; e += SCAN_B * 256) {
        int d = dst[e];
        int p = atomicAdd(&g_off[d], 1);
        g_permsrc[p] = src[e];
        const float4* sp = (const float4*)(ea + (size_t)e * 8);
        float4 a0 = sp[0], a1 = sp[1];
        float eav[8] = {a0.x, a0.y, a0.z, a0.w, a1.x, a1.y, a1.z, a1.w};
#pragma unroll
        for (int l = 0; l < NL; l++) {
            float o[4];
#pragma unroll
            for (int h = 0; h < 4; h++) {
                float s = 0.f;
#pragma unroll
                for (int j = 0; j < 8; j++) s = fmaf(eav[j], scc[l * 32 + j * 4 + h], s);
                o[h] = s;
            }
            *(float4*)&g_aedg[(size_t)l * NE * 4 + (size_t)p * 4] =
                make_float4(o[0], o[1], o[2], o[3]);
        }
    }
    __syncthreads();
    if (t == 0) {
        int old = atomicAdd(&g_donecnt, 1);
        if (old == SCAN_B - 1) {
            g_barcnt = 0;
            g_donecnt = 0;
            __threadfence();
        }
    }
}

// ---------------- GEMM1 via wmma HMMA: xl = h_t @ W[l], fused att dots + fp16 store ----
// dyn smem: As f32[128*132] | Ah half[128*64] | Bh half[64*128] | sas[128] | sad[128]
__global__ __launch_bounds__(256) void k_gemm1(const float* __restrict__ B,
                                               const float* __restrict__ as_,
                                               const float* __restrict__ ad_) {
    extern __shared__ float Q[];
    float* As = Q;                              // 16896 floats
    __half* Ah = (__half*)(Q + 16896);          // 8192 halves (4096 floats)
    __half* Bh = (__half*)(Q + 16896 + 4096);   // 8192 halves (4096 floats)
    float* sas = Q + 16896 + 8192;
    float* sad = sas + 128;
    int tid = threadIdx.x;
    int wid = tid >> 5;
    int row0 = blockIdx.x * 128;
    int col0 = blockIdx.y * 128;
    // load A tile (fp32 -> fp16) and B slice (fp32 -> fp16)
#pragma unroll
    for (int i = 0; i < 32; i++) {
        int idx = tid + i * 256;
        int r = idx >> 6, k = idx & 63;
        int rr = row0 + r;
        Ah[r * 64 + k] = __float2half((rr < NT) ? g_ht[(size_t)rr * 64 + k] : 0.f);
    }
#pragma unroll
    for (int i = 0; i < 32; i++) {
        int idx = tid + i * 256;
        int k = idx >> 7, c = idx & 127;
        Bh[k * 128 + c] = __float2half(B[(size_t)k * HE + col0 + c]);
    }
    if (tid < 128) { sas[tid] = __ldg(&as_[col0 + tid]); sad[tid] = __ldg(&ad_[col0 + tid]); }
    __syncthreads();
    // wmma: warp wid -> rows [wid*16, +16), 8 N-tiles of 16 covering 128 cols
    wmma::fragment<wmma::matrix_a, 16, 16, 16, __half, wmma::row_major> a_frag;
    wmma::fragment<wmma::matrix_b, 16, 16, 16, __half, wmma::row_major> b_frag;
    wmma::fragment<wmma::accumulator, 16, 16, 16, float> c_frag[8];
#pragma unroll
    for (int nf = 0; nf < 8; nf++) wmma::fill_fragment(c_frag[nf], 0.f);
#pragma unroll
    for (int k0 = 0; k0 < 64; k0 += 16) {
        wmma::load_matrix_sync(a_frag, Ah + wid * 16 * 64 + k0, 64);
#pragma unroll
        for (int nf = 0; nf < 8; nf++) {
            wmma::load_matrix_sync(b_frag, Bh + k0 * 128 + nf * 16, 128);
            wmma::mma_sync(c_frag[nf], a_frag, b_frag, c_frag[nf]);
        }
    }
#pragma unroll
    for (int nf = 0; nf < 8; nf++)
        wmma::store_matrix_sync(&As[wid * 16 * 132 + nf * 16], c_frag[nf], 132,
                                wmma::mem_row_major);
    __syncthreads();
    // epilogue: per-row fp16 store + attention dots (from the same rounded values)
    if (tid < 128) {
        int gr = row0 + tid;
        if (gr < NT) {
            const float* rowp = &As[tid * 132];
            __half2* hx = (__half2*)&g_xlh[(size_t)gr * HE + col0];
            float ps0 = 0, pd0 = 0, ps1 = 0, pd1 = 0;
#pragma unroll
            for (int i = 0; i < 32; i++) {
                float2 v = make_float2(rowp[i * 4], rowp[i * 4 + 1]);
                float2 w2 = make_float2(rowp[i * 4 + 2], rowp[i * 4 + 3]);
                __half2 h0 = __float22half2_rn(v);
                __half2 h1 = __float22half2_rn(w2);
                hx[i * 2] = h0;
                hx[i * 2 + 1] = h1;
                float2 f0 = __half22float2(h0);
                float2 f1 = __half22float2(h1);
                int c = i * 4;
                if (c < 64) {
                    ps0 = fmaf(f0.x, sas[c], ps0);     pd0 = fmaf(f0.x, sad[c], pd0);
                    ps0 = fmaf(f0.y, sas[c + 1], ps0); pd0 = fmaf(f0.y, sad[c + 1], pd0);
                    ps0 = fmaf(f1.x, sas[c + 2], ps0); pd0 = fmaf(f1.x, sad[c + 2], pd0);
                    ps0 = fmaf(f1.y, sas[c + 3], ps0); pd0 = fmaf(f1.y, sad[c + 3], pd0);
                } else {
                    ps1 = fmaf(f0.x, sas[c], ps1);     pd1 = fmaf(f0.x, sad[c], pd1);
                    ps1 = fmaf(f0.y, sas[c + 1], ps1); pd1 = fmaf(f0.y, sad[c + 1], pd1);
                    ps1 = fmaf(f1.x, sas[c + 2], ps1); pd1 = fmaf(f1.x, sad[c + 2], pd1);
                    ps1 = fmaf(f1.y, sas[c + 3], ps1); pd1 = fmaf(f1.y, sad[c + 3], pd1);
                }
            }
            int h0i = blockIdx.y * 2, h1i = h0i + 1;
            g_asrc[gr * 4 + h0i] = ps0; g_adst[gr * 4 + h0i] = pd0;
            g_asrc[gr * 4 + h1i] = ps1; g_adst[gr * 4 + h1i] = pd1;
        }
    }
}

// ---------------- attention + aggregate (warp/node; fp16 gather; fp16 gout) ----------
__global__ __launch_bounds__(128, 8) void k_agg(const float* __restrict__ gatb, int layer) {
    __shared__ float slp[4];
    __shared__ float sex[4][WCAP * 4];
    if (threadIdx.x < 4) slp[threadIdx.x] = g_loopae[layer * 4 + threadIdx.x];
    __syncthreads();
    int warp = blockIdx.x * 4 + (threadIdx.x >> 5);
    if (warp >= NT) return;
    int w = threadIdx.x >> 5;
    int lane = threadIdx.x & 31;
    int n = warp;
    const float* aedg = g_aedg + (size_t)layer * NE * 4;
    int beg = g_rowptr[n], end = g_rowptr[n + 1];
    float4 t4 = *(const float4*)&g_adst[n * 4];
    float ad[4] = {t4.x, t4.y, t4.z, t4.w};
    t4 = *(const float4*)&g_asrc[n * 4];
    float lex[4], dn[4];
    {
        float an[4] = {t4.x, t4.y, t4.z, t4.w};
#pragma unroll
        for (int h = 0; h < 4; h++) {
            float v = an[h] + ad[h] + slp[h];
            v = v > 0.f ? v : 0.2f * v;
            lex[h] = __expf(v);
            dn[h] = 0.f;
        }
    }
    int sreg[2] = {0, 0};
#pragma unroll
    for (int i = 0; i < 2; i++) {
        int e = beg + i * 32 + lane;
        if (e < end) {
            int s = g_permsrc[e];
            sreg[i] = s;
            float4 a4 = *(const float4*)&g_asrc[s * 4];
            float4 e4 = __ldg((const float4*)&aedg[(size_t)e * 4]);
            float as4[4] = {a4.x, a4.y, a4.z, a4.w};
            float ae4[4] = {e4.x, e4.y, e4.z, e4.w};
#pragma unroll
            for (int h = 0; h < 4; h++) {
                float v = as4[h] + ad[h] + ae4[h];
                v = v > 0.f ? v : 0.2f * v;
                float ex = __expf(v);
                sex[w][(i * 32 + lane) * 4 + h] = ex;
                dn[h] += ex;
            }
        }
    }
    for (int e = beg + WCAP + lane; e < end; e += 32) {
        int s = g_permsrc[e];
        float4 a4 = *(const float4*)&g_asrc[s * 4];
        float4 e4 = __ldg((const float4*)&aedg[(size_t)e * 4]);
        float as4[4] = {a4.x, a4.y, a4.z, a4.w};
        float ae4[4] = {e4.x, e4.y, e4.z, e4.w};
        float ex4[4];
#pragma unroll
        for (int h = 0; h < 4; h++) {
            float v = as4[h] + ad[h] + ae4[h];
            v = v > 0.f ? v : 0.2f * v;
            ex4[h] = __expf(v);
            dn[h] += ex4[h];
        }
        *(float4*)&g_exbuf[(size_t)e * 4] = make_float4(ex4[0], ex4[1], ex4[2], ex4[3]);
    }
#pragma unroll
    for (int off = 16; off >= 1; off >>= 1)
#pragma unroll
        for (int h = 0; h < 4; h++) dn[h] += __shfl_xor_sync(0xffffffffu, dn[h], off);
    int hh = lane >> 3;
    float myrc, mylex;
    {
        float rc[4];
#pragma unroll
        for (int h = 0; h < 4; h++) rc[h] = 1.f / (dn[h] + lex[h] + 1e-16f);
        myrc = hh == 0 ? rc[0] : hh == 1 ? rc[1] : hh == 2 ? rc[2] : rc[3];
        mylex = hh == 0 ? lex[0] : hh == 1 ? lex[1] : hh == 2 ? lex[2] : lex[3];
    }
    __syncwarp();
    int col0 = lane * 8;
    const __half* xbase = g_xlh + col0;
    float acc[8] = {0, 0, 0, 0, 0, 0, 0, 0};
    const float* mysex = sex[w];
    int deg = end - beg;
    int e = 0;
    for (; e + 4 <= deg && e + 4 <= WCAP; e += 4) {
        int s0 = __shfl_sync(0xffffffffu, sreg[e >> 5], e & 31);
        int s1 = __shfl_sync(0xffffffffu, sreg[(e + 1) >> 5], (e + 1) & 31);
        int s2 = __shfl_sync(0xffffffffu, sreg[(e + 2) >> 5], (e + 2) & 31);
        int s3 = __shfl_sync(0xffffffffu, sreg[(e + 3) >> 5], (e + 3) & 31);
        float w0 = mysex[e * 4 + hh];
        float w1 = mysex[(e + 1) * 4 + hh];
        float w2 = mysex[(e + 2) * 4 + hh];
        float w3 = mysex[(e + 3) * 4 + hh];
        uint4 q0 = __ldg((const uint4*)(xbase + (size_t)s0 * HE));
        uint4 q1 = __ldg((const uint4*)(xbase + (size_t)s1 * HE));
        uint4 q2 = __ldg((const uint4*)(xbase + (size_t)s2 * HE));
        uint4 q3 = __ldg((const uint4*)(xbase + (size_t)s3 * HE));
#pragma unroll
        for (int pi = 0; pi < 4; pi++) {
            uint4 q = pi == 0 ? q0 : pi == 1 ? q1 : pi == 2 ? q2 : q3;
            float we = pi == 0 ? w0 : pi == 1 ? w1 : pi == 2 ? w2 : w3;
            const __half2* hp = (const __half2*)&q;
            float2 f0 = __half22float2(hp[0]);
            float2 f1 = __half22float2(hp[1]);
            float2 f2 = __half22float2(hp[2]);
            float2 f3 = __half22float2(hp[3]);
            acc[0] = fmaf(we, f0.x, acc[0]); acc[1] = fmaf(we, f0.y, acc[1]);
            acc[2] = fmaf(we, f1.x, acc[2]); acc[3] = fmaf(we, f1.y, acc[3]);
            acc[4] = fmaf(we, f2.x, acc[4]); acc[5] = fmaf(we, f2.y, acc[5]);
            acc[6] = fmaf(we, f3.x, acc[6]); acc[7] = fmaf(we, f3.y, acc[7]);
        }
    }
    for (; e < deg && e < WCAP; e++) {
        int s = __shfl_sync(0xffffffffu, sreg[e >> 5], e & 31);
        float we = mysex[e * 4 + hh];
        uint4 q = __ldg((const uint4*)(xbase + (size_t)s * HE));
        const __half2* hp = (const __half2*)&q;
        float2 f0 = __half22float2(hp[0]);
        float2 f1 = __half22float2(hp[1]);
        float2 f2 = __half22float2(hp[2]);
        float2 f3 = __half22float2(hp[3]);
        acc[0] = fmaf(we, f0.x, acc[0]); acc[1] = fmaf(we, f0.y, acc[1]);
        acc[2] = fmaf(we, f1.x, acc[2]); acc[3] = fmaf(we, f1.y, acc[3]);
        acc[4] = fmaf(we, f2.x, acc[4]); acc[5] = fmaf(we, f2.y, acc[5]);
        acc[6] = fmaf(we, f3.x, acc[6]); acc[7] = fmaf(we, f3.y, acc[7]);
    }
    for (int ee = beg + WCAP; ee < end; ee++) {
        int s = g_permsrc[ee];
        float we = __ldg(&g_exbuf[(size_t)ee * 4 + hh]);
        uint4 q = __ldg((const uint4*)(xbase + (size_t)s * HE));
        const __half2* hp = (const __half2*)&q;
        float2 f0 = __half22float2(hp[0]);
        float2 f1 = __half22float2(hp[1]);
        float2 f2 = __half22float2(hp[2]);
        float2 f3 = __half22float2(hp[3]);
        acc[0] = fmaf(we, f0.x, acc[0]); acc[1] = fmaf(we, f0.y, acc[1]);
        acc[2] = fmaf(we, f1.x, acc[2]); acc[3] = fmaf(we, f1.y, acc[3]);
        acc[4] = fmaf(we, f2.x, acc[4]); acc[5] = fmaf(we, f2.y, acc[5]);
        acc[6] = fmaf(we, f3.x, acc[6]); acc[7] = fmaf(we, f3.y, acc[7]);
    }
    {
        uint4 q = __ldg((const uint4*)(xbase + (size_t)n * HE));
        const __half2* hp = (const __half2*)&q;
        float2 f0 = __half22float2(hp[0]);
        float2 f1 = __half22float2(hp[1]);
        float2 f2 = __half22float2(hp[2]);
        float2 f3 = __half22float2(hp[3]);
        acc[0] = fmaf(mylex, f0.x, acc[0]); acc[1] = fmaf(mylex, f0.y, acc[1]);
        acc[2] = fmaf(mylex, f1.x, acc[2]); acc[3] = fmaf(mylex, f1.y, acc[3]);
        acc[4] = fmaf(mylex, f2.x, acc[4]); acc[5] = fmaf(mylex, f2.y, acc[5]);
        acc[6] = fmaf(mylex, f3.x, acc[6]); acc[7] = fmaf(mylex, f3.y, acc[7]);
        const float4* bp = (const float4*)(gatb + col0);
        float4 b0 = __ldg(bp), b1 = __ldg(bp + 1);
        float o0 = fmaf(acc[0], myrc, b0.x), o1 = fmaf(acc[1], myrc, b0.y);
        float o2 = fmaf(acc[2], myrc, b0.z), o3 = fmaf(acc[3], myrc, b0.w);
        float o4 = fmaf(acc[4], myrc, b1.x), o5 = fmaf(acc[5], myrc, b1.y);
        float o6 = fmaf(acc[6], myrc, b1.z), o7 = fmaf(acc[7], myrc, b1.w);
        uint4 oq;
        __half2* oh = (__half2*)&oq;
        oh[0] = __float22half2_rn(make_float2(o0, o1));
        oh[1] = __float22half2_rn(make_float2(o2, o3));
        oh[2] = __float22half2_rn(make_float2(o4, o5));
        oh[3] = __float22half2_rn(make_float2(o6, o7));
        *(uint4*)(g_gout + (size_t)n * HE + col0) = oq;
    }
}

// ---------------- proj GEMM via wmma HMMA (fp16 A from g_gout, fp16 B in smem) -------
// + elu + residual + LN (+fused taskhead & copyout when last)
__global__ __launch_bounds__(256) void k_proj_ln(const float* __restrict__ B,
                                                 const float* __restrict__ pb,
                                                 const float* __restrict__ lg,
                                                 const float* __restrict__ lb,
                                                 int last,
                                                 const float* __restrict__ tW1,
                                                 const float* __restrict__ tb1,
                                                 const float* __restrict__ tW2,
                                                 const float* __restrict__ tb2,
                                                 float* __restrict__ out) {
    extern __shared__ float P[];
    float* As = P;                       // 8704 floats
    __half* Bh = (__half*)(P + 8704);    // 16384 halves = 8192 floats
    float* slg = P + 8704 + 8192;
    float* slb = slg + 64;
    float* spb = slb + 64;
    __shared__ float sW1[64 * 32];
    __shared__ float sW2[32];
    __shared__ float sb1[32];
    int tid = threadIdx.x;
    int wid = tid >> 5;
    int row0 = blockIdx.x * 128;
    if (tid < 64) { slg[tid] = __ldg(&lg[tid]); slb[tid] = __ldg(&lb[tid]); spb[tid] = __ldg(&pb[tid]); }
    if (last) {
        for (int i = tid; i < 64 * 32; i += 256) sW1[i] = tW1[i];
        if (tid < 32) { sW2[tid] = tW2[tid]; sb1[tid] = tb1[tid]; }
    }
    for (int i = tid; i < 256 * 64; i += 256) Bh[i] = __float2half(B[i]);
    __syncthreads();
    wmma::fragment<wmma::matrix_a, 16, 16, 16, __half, wmma::row_major> a_frag;
    wmma::fragment<wmma::matrix_b, 16, 16, 16, __half, wmma::row_major> b_frag;
    wmma::fragment<wmma::accumulator, 16, 16, 16, float> c_frag[4];
#pragma unroll
    for (int nf = 0; nf < 4; nf++) wmma::fill_fragment(c_frag[nf], 0.f);
    const __half* arow = g_gout + (size_t)(row0 + wid * 16) * HE;
#pragma unroll 4
    for (int k0 = 0; k0 < 256; k0 += 16) {
        wmma::load_matrix_sync(a_frag, arow + k0, HE);
#pragma unroll
        for (int nf = 0; nf < 4; nf++) {
            wmma::load_matrix_sync(b_frag, Bh + k0 * 64 + nf * 16, 64);
            wmma::mma_sync(c_frag[nf], a_frag, b_frag, c_frag[nf]);
        }
    }
#pragma unroll
    for (int nf = 0; nf < 4; nf++)
        wmma::store_matrix_sync(&As[wid * 16 * 68 + nf * 16], c_frag[nf], 68,
                                wmma::mem_row_major);
    __syncthreads();
    if (tid < 128) {
        int gr = row0 + tid;
        if (gr < NT) {
            float h[64];
            float s1 = 0.f, s2 = 0.f;
#pragma unroll
            for (int i = 0; i < 16; i++) {
                float4 a = *(float4*)&As[tid * 68 + i * 4];
                a.x += spb[i * 4];     a.x = (a.x > 0.f) ? a.x : (__expf(a.x) - 1.f);
                a.y += spb[i * 4 + 1]; a.y = (a.y > 0.f) ? a.y : (__expf(a.y) - 1.f);
                a.z += spb[i * 4 + 2]; a.z = (a.z > 0.f) ? a.z : (__expf(a.z) - 1.f);
                a.w += spb[i * 4 + 3]; a.w = (a.w > 0.f) ? a.w : (__expf(a.w) - 1.f);
                float4 b = *(const float4*)&g_ht[(size_t)gr * 64 + i * 4];
                float v0 = a.x + b.x, v1 = a.y + b.y, v2 = a.z + b.z, v3 = a.w + b.w;
                h[i * 4] = v0; h[i * 4 + 1] = v1; h[i * 4 + 2] = v2; h[i * 4 + 3] = v3;
                s1 += v0 + v1 + v2 + v3;
                s2 += v0 * v0 + v1 * v1 + v2 * v2 + v3 * v3;
            }
            float mu = s1 * (1.f / 64.f);
            float var = s2 * (1.f / 64.f) - mu * mu;
            float rs = rsqrtf(var + 1e-5f);
            const int OFF_HT = NT + NG;
#pragma unroll
            for (int i = 0; i < 16; i++) {
                float4 o;
                o.x = (h[i * 4] - mu) * rs * slg[i * 4] + slb[i * 4];
                o.y = (h[i * 4 + 1] - mu) * rs * slg[i * 4 + 1] + slb[i * 4 + 1];
                o.z = (h[i * 4 + 2] - mu) * rs * slg[i * 4 + 2] + slb[i * 4 + 2];
                o.w = (h[i * 4 + 3] - mu) * rs * slg[i * 4 + 3] + slb[i * 4 + 3];
                *(float4*)&g_ht[(size_t)gr * 64 + i * 4] = o;
                h[i * 4] = o.x; h[i * 4 + 1] = o.y; h[i * 4 + 2] = o.z; h[i * 4 + 3] = o.w;
                if (last) *(float4*)&out[OFF_HT + (size_t)gr * 64 + i * 4] = o;
            }
            if (last) {
                float logit = __ldg(tb2);
#pragma unroll
                for (int half = 0; half < 2; half++) {
                    float hid[16];
#pragma unroll
                    for (int j = 0; j < 16; j++) hid[j] = sb1[half * 16 + j];
#pragma unroll 4
                    for (int k = 0; k < 64; k++) {
                        float rv = h[k];
#pragma unroll
                        for (int j = 0; j < 16; j++)
                            hid[j] = fmaf(rv, sW1[k * 32 + half * 16 + j], hid[j]);
                    }
#pragma unroll
                    for (int j = 0; j < 16; j++)
                        logit = fmaf(fmaxf(hid[j], 0.f), sW2[half * 16 + j], logit);
                }
                out[gr] = logit;
            }
        }
    }
}

// ---------------- task pooling (128 rows/block) ----------------
__global__ void k_pool_task(const int* __restrict__ batch) {
    int c = threadIdx.x;
    int r0 = blockIdx.x * 128;
    int r1 = min(r0 + 128, NT);
    float acc = 0.f; int cg = -1; int cnt = 0;
    for (int r = r0; r < r1; r++) {
        int g = batch[r];
        if (g != cg) {
            if (cg >= 0) {
                atomicAdd(&g_tp[cg * 64 + c], acc);
                if (c == 0) atomicAdd(&g_cntt[cg], cnt);
            }
            cg = g; acc = 0.f; cnt = 0;
        }
        acc += g_ht[(size_t)r * 64 + c];
        cnt++;
    }
    if (cg >= 0) {
        atomicAdd(&g_tp[cg * 64 + c], acc);
        if (c == 0) atomicAdd(&g_cntt[cg], cnt);
    }
}

// ---------------- value head (inlines proc pooling + h_p copy-out; resets pool state) --
__global__ void k_value(const float* __restrict__ W1, const float* __restrict__ b1,
                        const float* __restrict__ W2, const float* __restrict__ b2,
                        const int* __restrict__ pbatch, float* __restrict__ out) {
    __shared__ float ge[NG * 128];
    __shared__ float red[512];
    __shared__ int sb[NP];
    int t = threadIdx.x;
    if (t < NP) sb[t] = pbatch[t];
    __syncthreads();
    const int OFF_HP = NT + NG + NT * EMB;
    for (int k = t; k < NP * EMB; k += 512) out[OFF_HP + k] = g_hp[k];
    for (int idx = t; idx < NG * 128; idx += 512) {
        int g = idx >> 7, k = idx & 127;
        float v;
        if (k < 64) {
            v = g_tp[g * 64 + k] / fmaxf((float)g_cntt[g], 1.f);
        } else {
            int j = k - 64;
            float s = 0.f; int cnt = 0;
            for (int r = 0; r < NP; r++) {
                if (sb[r] == g) { s += g_hp[r * 64 + j]; cnt++; }
            }
            v = s / fmaxf((float)cnt, 1.f);
        }
        ge[idx] = v;
    }
    __syncthreads();
    for (int idx = t; idx < NG * EMB; idx += 512) g_tp[idx] = 0.f;
    if (t < NG) g_cntt[t] = 0;
    int g = t >> 6, j = t & 63;
    float a = b1[j];
#pragma unroll 4
    for (int k = 0; k < 128; k++) a = fmaf(ge[g * 128 + k], W1[k * 64 + j], a);
    red[t] = fmaxf(a, 0.f) * W2[j];
    __syncthreads();
#pragma unroll
    for (int off = 32; off >= 1; off >>= 1) {
        if (j < off) red[t] += red[t + off];
        __syncthreads();
    }
    if (j == 0) out[NT + g] = red[t] + b2[0];
}

// ---------------- launch ----------------
extern "C" void kernel_launch(void* const* d_in, const int* in_sizes, int n_in,
                              void* d_out, int out_size) {
    const float *x_task, *x_proc, *edge_attr, *W_task, *b_task, *W_proc, *b_proc;
    const float *gat_W, *gat_We, *att_src, *att_dst, *att_edge, *gat_b, *proj_W, *proj_b;
    const float *ln_g, *ln_b, *pt_W1, *pt_b1, *pt_W2, *pt_b2, *v_W1, *v_b1, *v_W2, *v_b2;
    const int *edge_index, *task_batch, *proc_batch;

    if (in_sizes[2] == 2 * NE) {  // setup_inputs dict order
        x_task = (const float*)d_in[0];  x_proc = (const float*)d_in[1];
        edge_index = (const int*)d_in[2]; edge_attr = (const float*)d_in[3];
        task_batch = (const int*)d_in[4]; proc_batch = (const int*)d_in[5];
        W_task = (const float*)d_in[6];  b_task = (const float*)d_in[7];
        W_proc = (const float*)d_in[8];  b_proc = (const float*)d_in[9];
        gat_W = (const float*)d_in[10];  gat_We = (const float*)d_in[11];
        att_src = (const float*)d_in[12]; att_dst = (const float*)d_in[13];
        att_edge = (const float*)d_in[14]; gat_b = (const float*)d_in[15];
        proj_W = (const float*)d_in[16]; proj_b = (const float*)d_in[17];
        ln_g = (const float*)d_in[18];   ln_b = (const float*)d_in[19];
        pt_W1 = (const float*)d_in[20];  pt_b1 = (const float*)d_in[21];
        pt_W2 = (const float*)d_in[22];  pt_b2 = (const float*)d_in[23];
        v_W1 = (const float*)d_in[24];   v_b1 = (const float*)d_in[25];
        v_W2 = (const float*)d_in[26];   v_b2 = (const float*)d_in[27];
    } else {  // reference() signature order
        x_task = (const float*)d_in[0];  x_proc = (const float*)d_in[1];
        edge_attr = (const float*)d_in[2];
        W_task = (const float*)d_in[3];  b_task = (const float*)d_in[4];
        W_proc = (const float*)d_in[5];  b_proc = (const float*)d_in[6];
        gat_W = (const float*)d_in[7];   gat_We = (const float*)d_in[8];
        att_src = (const float*)d_in[9]; att_dst = (const float*)d_in[10];
        att_edge = (const float*)d_in[11]; gat_b = (const float*)d_in[12];
        proj_W = (const float*)d_in[13]; proj_b = (const float*)d_in[14];
        ln_g = (const float*)d_in[15];   ln_b = (const float*)d_in[16];
        pt_W1 = (const float*)d_in[17];  pt_b1 = (const float*)d_in[18];
        pt_W2 = (const float*)d_in[19];  pt_b2 = (const float*)d_in[20];
        v_W1 = (const float*)d_in[21];   v_b1 = (const float*)d_in[22];
        v_W2 = (const float*)d_in[23];   v_b2 = (const float*)d_in[24];
        edge_index = (const int*)d_in[25];
        task_batch = (const int*)d_in[26]; proc_batch = (const int*)d_in[27];
    }
    float* out = (float*)d_out;
    const int* e_src = edge_index;
    const int* e_dst = edge_index + NE;

    const int SMEM_G1 = (16896 + 8192 + 256) * 4;  // As + Ah/Bh + sas/sad
    const int SMEM_PJ = (8704 + 8192 + 192) * 4;   // As + Bh + slg/slb/spb
    cudaFuncSetAttribute(k_gemm1, cudaFuncAttributeMaxDynamicSharedMemorySize, SMEM_G1);
    cudaFuncSetAttribute(k_proj_ln, cudaFuncAttributeMaxDynamicSharedMemorySize, SMEM_PJ);

    cudaStream_t s2;
    cudaStreamCreateWithFlags(&s2, cudaStreamNonBlocking);
    cudaEvent_t evA, evB;
    cudaEventCreateWithFlags(&evA, cudaEventDisableTiming);
    cudaEventCreateWithFlags(&evB, cudaEventDisableTiming);

    k_setup<<<NT / 4 + 64 + 512, 256>>>(x_task, W_task, b_task, x_proc, W_proc, b_proc,
                                        edge_attr, e_dst);
    cudaEventRecord(evA, 0);
    cudaStreamWaitEvent(s2, evA, 0);
    k_gemm1<<<dim3((NTP + 127) / 128, 2), 256, SMEM_G1, s2>>>(gat_W, att_src, att_dst);
    k_csr<<<SCAN_B, 256>>>(e_src, e_dst, edge_attr, gat_We, att_edge);
    cudaEventRecord(evB, s2);
    cudaStreamWaitEvent(0, evB, 0);

    for (int l = 0; l < NL; l++) {
        if (l > 0)
            k_gemm1<<<dim3((NTP + 127) / 128, 2), 256, SMEM_G1>>>(
                gat_W + (size_t)l * EMB * HE, att_src + l * H * EMB, att_dst + l * H * EMB);
        k_agg<<<NT / 4, 128>>>(gat_b + l * HE, l);
        k_proj_ln<<<(NTP + 127) / 128, 256, SMEM_PJ>>>(
            proj_W + (size_t)l * HE * EMB, proj_b + l * EMB, ln_g + l * EMB, ln_b + l * EMB,
            (l == NL - 1) ? 1 : 0, pt_W1, pt_b1, pt_W2, pt_b2, out);
    }

    k_pool_task<<<(NT + 127) / 128, 64>>>(task_batch);
    k_value<<<1, 512>>>(v_W1, v_b1, v_W2, v_b2, proc_batch, out);

    cudaEventDestroy(evA);
    cudaEventDestroy(evB);
    cudaStreamDestroy(s2);
}

// round 15
// speedup vs baseline: 1.1277x; 1.1277x over previous
#include <cuda_runtime.h>
#include <cuda_fp16.h>
#include <mma.h>
#include <math.h>

using namespace nvcuda;

#define NT 50000
#define NTP 50048    // NT padded to 128 for wmma row tiles
#define NP 256
#define NE 800000
#define EMB 64
#define H 4
#define HE 256       // H*EMB
#define NL 3
#define EDIM 8
#define TDIM 16
#define PDIM 8
#define NG 8
#define SCAN_B 196   // ceil(NT/256)
#define WCAP 64      // per-warp smem edge stash (deg <= 64 fast path)

// ---------------- f32x2 packed-FMA helpers ----------------
union U2 { float4 f4; unsigned long long u[2]; };

__device__ __forceinline__ unsigned long long dup2(float x) {
    unsigned long long r;
    asm("mov.b64 %0, {%1, %1};" : "=l"(r) : "f"(x));
    return r;
}
__device__ __forceinline__ void ffma2(unsigned long long& d, unsigned long long a,
                                      unsigned long long b) {
    asm("fma.rn.f32x2 %0, %1, %2, %0;" : "+l"(d) : "l"(a), "l"(b));
}
__device__ __forceinline__ float2 unpack2(unsigned long long v) {
    float2 r;
    asm("mov.b64 {%0, %1}, %2;" : "=f"(r.x), "=f"(r.y) : "l"(v));
    return r;
}

// ---------------- scratch (static __device__, no allocs) ----------------
// state-recycling invariant: g_deg, g_meanea, g_tp, g_cntt, g_barcnt, g_donecnt
// are zero at entry (zero-init at load; reset by their consumers every run).
// g_gout rows [NT, NTP) stay zero forever (never written) -> safe wmma loads.
__device__ __half  g_xlh[(size_t)NT * HE];      // fp16 transformed feats (only copy)
__device__ __half  g_gout[(size_t)NTP * HE];    // fp16 GAT aggregation output (padded)
__device__ float   g_ht[(size_t)NT * EMB];
__device__ float   g_hp[NP * EMB];
__device__ float   g_asrc[NT * H];
__device__ float   g_adst[NT * H];
__device__ float   g_exbuf[(size_t)NE * H];     // overflow (deg > WCAP) ex only
__device__ float   g_aedg[(size_t)NL * NE * H]; // per-edge per-layer attention dots (CSR order)
__device__ int     g_permsrc[NE];
__device__ int     g_rowptr[NT + 1];
__device__ int     g_deg[NT];
__device__ int     g_off[NT];
__device__ int     g_bsum[SCAN_B];
__device__ float   g_meanea[EDIM];
__device__ float   g_c[NL * EDIM * H];
__device__ float   g_loopae[NL * H];
__device__ float   g_tp[NG * EMB];
__device__ int     g_cntt[NG];
__device__ int     g_barcnt;
__device__ int     g_donecnt;

// ---------------- fused setup: task embed + proc embed + meanea + dst hist ----------
__global__ void k_setup(const float* __restrict__ xt, const float* __restrict__ Wt,
                        const float* __restrict__ bt, const float* __restrict__ xp,
                        const float* __restrict__ Wp, const float* __restrict__ bp,
                        const float* __restrict__ ea, const int* __restrict__ dst) {
    int b = blockIdx.x;
    int tid = threadIdx.x;
    if (b < NT / 4) {
        __shared__ float sW[TDIM * EMB];
        __shared__ float sb[EMB];
        __shared__ float sx[4][TDIM];
        int tx = tid & 63, ty = tid >> 6;
        for (int i = tid; i < TDIM * EMB; i += 256) sW[i] = Wt[i];
        if (tid < EMB) sb[tid] = bt[tid];
        int n = b * 4 + ty;
        if (tx < TDIM) sx[ty][tx] = xt[(size_t)n * TDIM + tx];
        __syncthreads();
        float a = sb[tx];
#pragma unroll
        for (int k = 0; k < TDIM; k++) a = fmaf(sx[ty][k], sW[k * EMB + tx], a);
        g_ht[(size_t)n * EMB + tx] = a;
    } else if (b < NT / 4 + 64) {
        int idx = (b - NT / 4) * 256 + tid;
        int n = idx >> 6, c = idx & 63;
        float a = bp[c];
#pragma unroll
        for (int k = 0; k < PDIM; k++)
            a = fmaf(__ldg(&xp[n * PDIM + k]), __ldg(&Wp[k * EMB + c]), a);
        g_hp[idx] = a;
    } else {
        int i = (b - NT / 4 - 64) * 256 + tid;
        int stride = 512 * 256;
        float acc[8] = {0, 0, 0, 0, 0, 0, 0, 0};
        for (int e = i; e < NE; e += stride) {
            const float4* p = (const float4*)(ea + (size_t)e * 8);
            float4 a0 = p[0], a1 = p[1];
            acc[0] += a0.x; acc[1] += a0.y; acc[2] += a0.z; acc[3] += a0.w;
            acc[4] += a1.x; acc[5] += a1.y; acc[6] += a1.z; acc[7] += a1.w;
            atomicAdd(&g_deg[dst[e]], 1);
        }
#pragma unroll
        for (int k = 0; k < 8; k++)
#pragma unroll
            for (int off = 16; off >= 1; off >>= 1)
                acc[k] += __shfl_xor_sync(0xffffffffu, acc[k], off);
        if ((tid & 31) == 0)
#pragma unroll
            for (int k = 0; k < 8; k++) atomicAdd(&g_meanea[k], acc[k]);
    }
}

// ---------------- grid barrier (all 196 blocks co-resident; self-resetting) --------
__device__ __forceinline__ void gbar(int target) {
    __syncthreads();
    if (threadIdx.x == 0) {
        __threadfence();
        atomicAdd(&g_barcnt, 1);
        while (atomicAdd(&g_barcnt, 0) < target) { }
        __threadfence();
    }
    __syncthreads();
}

// ---------------- CSR build: scan + cvec + scatter(+aedg all layers) in ONE kernel ----
__global__ void k_csr(const int* __restrict__ src, const int* __restrict__ dst,
                      const float* __restrict__ ea, const float* __restrict__ We,
                      const float* __restrict__ ae) {
    int b = blockIdx.x, t = threadIdx.x;
    __shared__ int sm[256];
    __shared__ float scc[NL * 32];
    int idx = b * 256 + t;
    int v = (idx < NT) ? g_deg[idx] : 0;
    sm[t] = v;
    __syncthreads();
    for (int off = 1; off < 256; off <<= 1) {
        int u = (t >= off) ? sm[t - off] : 0;
        __syncthreads();
        sm[t] += u;
        __syncthreads();
    }
    if (idx < NT) g_rowptr[idx] = sm[t] - v;
    if (t == 255) g_bsum[b] = sm[255];
    gbar(SCAN_B);
    if (b == 0) {
        int w = (t < SCAN_B) ? g_bsum[t] : 0;
        sm[t] = w;
        __syncthreads();
        for (int off = 1; off < 256; off <<= 1) {
            int u = (t >= off) ? sm[t - off] : 0;
            __syncthreads();
            sm[t] += u;
            __syncthreads();
        }
        if (t < SCAN_B) g_bsum[t] = sm[t] - w;
    } else if (b == 1) {
        if (t < NL * EDIM * H) {
            int l = t >> 5; int r = t & 31; int j = r >> 2; int h = r & 3;
            float s = 0.f;
            for (int d = 0; d < EMB; d++)
                s += We[((size_t)(l * EDIM + j)) * HE + h * EMB + d] * ae[(l * H + h) * EMB + d];
            g_c[t] = s;
        }
        __syncthreads();
        if (t < NL * H) {
            int l = t >> 2; int h = t & 3;
            float s = 0.f;
            for (int j = 0; j < EDIM; j++)
                s += (g_meanea[j] * (1.f / NE)) * g_c[l * 32 + j * 4 + h];
            g_loopae[t] = s;
        }
        __syncthreads();
        if (t < EDIM) g_meanea[t] = 0.f;
    }
    gbar(2 * SCAN_B);
    if (idx < NT) {
        int r = g_rowptr[idx] + g_bsum[b];
        g_rowptr[idx] = r;
        g_off[idx] = r;
        g_deg[idx] = 0;
    }
    if (b == 0 && t == 0) g_rowptr[NT] = NE;
    gbar(3 * SCAN_B);
    if (t < NL * 32) scc[t] = g_c[t];
    __syncthreads();
    for (int e = b * 256 + t; e < NE; e += SCAN_B * 256) {
        int d = dst[e];
        int p = atomicAdd(&g_off[d], 1);
        g_permsrc[p] = src[e];
        const float4* sp = (const float4*)(ea + (size_t)e * 8);
        float4 a0 = sp[0], a1 = sp[1];
        float eav[8] = {a0.x, a0.y, a0.z, a0.w, a1.x, a1.y, a1.z, a1.w};
#pragma unroll
        for (int l = 0; l < NL; l++) {
            float o[4];
#pragma unroll
            for (int h = 0; h < 4; h++) {
                float s = 0.f;
#pragma unroll
                for (int j = 0; j < 8; j++) s = fmaf(eav[j], scc[l * 32 + j * 4 + h], s);
                o[h] = s;
            }
            *(float4*)&g_aedg[(size_t)l * NE * 4 + (size_t)p * 4] =
                make_float4(o[0], o[1], o[2], o[3]);
        }
    }
    __syncthreads();
    if (t == 0) {
        int old = atomicAdd(&g_donecnt, 1);
        if (old == SCAN_B - 1) {
            g_barcnt = 0;
            g_donecnt = 0;
            __threadfence();
        }
    }
}

// ---------------- GEMM1: xl = h_t @ W[l] (f32x2, 128x128 tile), fused att dots ----------
// (reverted to the proven f32x2 version; writes fp16 g_xlh only)
__global__ __launch_bounds__(256) void k_gemm1(const float* __restrict__ B,
                                               const float* __restrict__ as_,
                                               const float* __restrict__ ad_) {
    extern __shared__ float Q[];
    float* As = Q;
    float* Bs = Q + 8448;
    float* sas = Q + 16640;
    float* sad = Q + 16768;
    int tid = threadIdx.x;
    int row0 = blockIdx.x * 128;
    int col0 = blockIdx.y * 128;
#pragma unroll
    for (int i = 0; i < 32; i++) {
        int idx = tid + i * 256;
        int r = idx >> 6, k = idx & 63;
        int rr = row0 + r;
        As[k * 132 + r] = (rr < NT) ? g_ht[(size_t)rr * 64 + k] : 0.f;
    }
#pragma unroll
    for (int i = 0; i < 32; i++) {
        int idx = tid + i * 256;
        int k = idx >> 7, c = idx & 127;
        Bs[k * 128 + c] = B[(size_t)k * HE + col0 + c];
    }
    if (tid < 128) { sas[tid] = __ldg(&as_[col0 + tid]); sad[tid] = __ldg(&ad_[col0 + tid]); }
    __syncthreads();
    int tx = tid & 15, ty = tid >> 4;
    unsigned long long acc[4][8];
#pragma unroll
    for (int rp = 0; rp < 4; rp++)
#pragma unroll
        for (int c = 0; c < 8; c++) acc[rp][c] = 0ull;
#pragma unroll 4
    for (int k = 0; k < 64; k++) {
        U2 a0, a1;
        a0.f4 = *(const float4*)&As[k * 132 + ty * 4];
        a1.f4 = *(const float4*)&As[k * 132 + 64 + ty * 4];
        float4 b0 = *(const float4*)&Bs[k * 128 + tx * 4];
        float4 b1 = *(const float4*)&Bs[k * 128 + 64 + tx * 4];
        unsigned long long bd[8] = {dup2(b0.x), dup2(b0.y), dup2(b0.z), dup2(b0.w),
                                    dup2(b1.x), dup2(b1.y), dup2(b1.z), dup2(b1.w)};
        unsigned long long ap[4] = {a0.u[0], a0.u[1], a1.u[0], a1.u[1]};
#pragma unroll
        for (int rp = 0; rp < 4; rp++)
#pragma unroll
            for (int c = 0; c < 8; c++) ffma2(acc[rp][c], ap[rp], bd[c]);
    }
    int h0 = blockIdx.y * 2, h1 = h0 + 1;
#pragma unroll
    for (int rp = 0; rp < 4; rp++) {
        float2 u[8];
#pragma unroll
        for (int c = 0; c < 8; c++) u[c] = unpack2(acc[rp][c]);
        int rA = row0 + ((rp >> 1) ? 64 : 0) + ty * 4 + (rp & 1) * 2;
        if (rA < NT) {
            __half2* hp = (__half2*)&g_xlh[(size_t)rA * HE + col0 + tx * 4];
            hp[0] = __float22half2_rn(make_float2(u[0].x, u[1].x));
            hp[1] = __float22half2_rn(make_float2(u[2].x, u[3].x));
            __half2* hq = (__half2*)&g_xlh[(size_t)rA * HE + col0 + 64 + tx * 4];
            hq[0] = __float22half2_rn(make_float2(u[4].x, u[5].x));
            hq[1] = __float22half2_rn(make_float2(u[6].x, u[7].x));
        }
        if (rA + 1 < NT) {
            __half2* hp = (__half2*)&g_xlh[(size_t)(rA + 1) * HE + col0 + tx * 4];
            hp[0] = __float22half2_rn(make_float2(u[0].y, u[1].y));
            hp[1] = __float22half2_rn(make_float2(u[2].y, u[3].y));
            __half2* hq = (__half2*)&g_xlh[(size_t)(rA + 1) * HE + col0 + 64 + tx * 4];
            hq[0] = __float22half2_rn(make_float2(u[4].y, u[5].y));
            hq[1] = __float22half2_rn(make_float2(u[6].y, u[7].y));
        }
        float ps0 = 0, pd0 = 0, ps1 = 0, pd1 = 0, qs0 = 0, qd0 = 0, qs1 = 0, qd1 = 0;
#pragma unroll
        for (int j = 0; j < 4; j++) {
            float s0 = sas[tx * 4 + j], d0 = sad[tx * 4 + j];
            float s1 = sas[64 + tx * 4 + j], d1 = sad[64 + tx * 4 + j];
            ps0 = fmaf(u[j].x, s0, ps0); pd0 = fmaf(u[j].x, d0, pd0);
            qs0 = fmaf(u[j].y, s0, qs0); qd0 = fmaf(u[j].y, d0, qd0);
            ps1 = fmaf(u[4 + j].x, s1, ps1); pd1 = fmaf(u[4 + j].x, d1, pd1);
            qs1 = fmaf(u[4 + j].y, s1, qs1); qd1 = fmaf(u[4 + j].y, d1, qd1);
        }
#pragma unroll
        for (int off = 8; off >= 1; off >>= 1) {
            ps0 += __shfl_xor_sync(0xffffffffu, ps0, off);
            pd0 += __shfl_xor_sync(0xffffffffu, pd0, off);
            ps1 += __shfl_xor_sync(0xffffffffu, ps1, off);
            pd1 += __shfl_xor_sync(0xffffffffu, pd1, off);
            qs0 += __shfl_xor_sync(0xffffffffu, qs0, off);
            qd0 += __shfl_xor_sync(0xffffffffu, qd0, off);
            qs1 += __shfl_xor_sync(0xffffffffu, qs1, off);
            qd1 += __shfl_xor_sync(0xffffffffu, qd1, off);
        }
        if (tx == 0) {
            if (rA < NT) {
                g_asrc[rA * 4 + h0] = ps0; g_adst[rA * 4 + h0] = pd0;
                g_asrc[rA * 4 + h1] = ps1; g_adst[rA * 4 + h1] = pd1;
            }
            if (rA + 1 < NT) {
                g_asrc[(rA + 1) * 4 + h0] = qs0; g_adst[(rA + 1) * 4 + h0] = qd0;
                g_asrc[(rA + 1) * 4 + h1] = qs1; g_adst[(rA + 1) * 4 + h1] = qd1;
            }
        }
    }
}

// ---------------- attention + aggregate (warp/node; fp16 gather; fp16 gout) ----------
__global__ __launch_bounds__(128, 8) void k_agg(const float* __restrict__ gatb, int layer) {
    __shared__ float sex[4][WCAP * 4];
    int warp = blockIdx.x * 4 + (threadIdx.x >> 5);
    if (warp >= NT) return;
    int w = threadIdx.x >> 5;
    int lane = threadIdx.x & 31;
    int n = warp;
    const float* aedg = g_aedg + (size_t)layer * NE * 4;
    int beg = g_rowptr[n], end = g_rowptr[n + 1];
    float4 t4 = *(const float4*)&g_adst[n * 4];
    float ad[4] = {t4.x, t4.y, t4.z, t4.w};
    t4 = *(const float4*)&g_asrc[n * 4];
    float lex[4], dn[4];
    {
        float an[4] = {t4.x, t4.y, t4.z, t4.w};
#pragma unroll
        for (int h = 0; h < 4; h++) {
            float v = an[h] + ad[h] + __ldg(&g_loopae[layer * 4 + h]);
            v = v > 0.f ? v : 0.2f * v;
            lex[h] = __expf(v);
            dn[h] = 0.f;
        }
    }
    int sreg[2] = {0, 0};
#pragma unroll
    for (int i = 0; i < 2; i++) {
        int e = beg + i * 32 + lane;
        if (e < end) {
            int s = g_permsrc[e];
            sreg[i] = s;
            float4 a4 = *(const float4*)&g_asrc[s * 4];
            float4 e4 = __ldg((const float4*)&aedg[(size_t)e * 4]);
            float as4[4] = {a4.x, a4.y, a4.z, a4.w};
            float ae4[4] = {e4.x, e4.y, e4.z, e4.w};
#pragma unroll
            for (int h = 0; h < 4; h++) {
                float v = as4[h] + ad[h] + ae4[h];
                v = v > 0.f ? v : 0.2f * v;
                float ex = __expf(v);
                sex[w][(i * 32 + lane) * 4 + h] = ex;
                dn[h] += ex;
            }
        }
    }
    for (int e = beg + WCAP + lane; e < end; e += 32) {
        int s = g_permsrc[e];
        float4 a4 = *(const float4*)&g_asrc[s * 4];
        float4 e4 = __ldg((const float4*)&aedg[(size_t)e * 4]);
        float as4[4] = {a4.x, a4.y, a4.z, a4.w};
        float ae4[4] = {e4.x, e4.y, e4.z, e4.w};
        float ex4[4];
#pragma unroll
        for (int h = 0; h < 4; h++) {
            float v = as4[h] + ad[h] + ae4[h];
            v = v > 0.f ? v : 0.2f * v;
            ex4[h] = __expf(v);
            dn[h] += ex4[h];
        }
        *(float4*)&g_exbuf[(size_t)e * 4] = make_float4(ex4[0], ex4[1], ex4[2], ex4[3]);
    }
#pragma unroll
    for (int off = 16; off >= 1; off >>= 1)
#pragma unroll
        for (int h = 0; h < 4; h++) dn[h] += __shfl_xor_sync(0xffffffffu, dn[h], off);
    int hh = lane >> 3;
    float myrc, mylex;
    {
        float rc[4];
#pragma unroll
        for (int h = 0; h < 4; h++) rc[h] = 1.f / (dn[h] + lex[h] + 1e-16f);
        myrc = hh == 0 ? rc[0] : hh == 1 ? rc[1] : hh == 2 ? rc[2] : rc[3];
        mylex = hh == 0 ? lex[0] : hh == 1 ? lex[1] : hh == 2 ? lex[2] : lex[3];
    }
    __syncwarp();
    int col0 = lane * 8;
    const __half* xbase = g_xlh + col0;
    float acc[8] = {0, 0, 0, 0, 0, 0, 0, 0};
    const float* mysex = sex[w];
    int deg = end - beg;
    int e = 0;
    for (; e + 4 <= deg && e + 4 <= WCAP; e += 4) {
        int s0 = __shfl_sync(0xffffffffu, sreg[e >> 5], e & 31);
        int s1 = __shfl_sync(0xffffffffu, sreg[(e + 1) >> 5], (e + 1) & 31);
        int s2 = __shfl_sync(0xffffffffu, sreg[(e + 2) >> 5], (e + 2) & 31);
        int s3 = __shfl_sync(0xffffffffu, sreg[(e + 3) >> 5], (e + 3) & 31);
        float w0 = mysex[e * 4 + hh];
        float w1 = mysex[(e + 1) * 4 + hh];
        float w2 = mysex[(e + 2) * 4 + hh];
        float w3 = mysex[(e + 3) * 4 + hh];
        uint4 q0 = __ldg((const uint4*)(xbase + (size_t)s0 * HE));
        uint4 q1 = __ldg((const uint4*)(xbase + (size_t)s1 * HE));
        uint4 q2 = __ldg((const uint4*)(xbase + (size_t)s2 * HE));
        uint4 q3 = __ldg((const uint4*)(xbase + (size_t)s3 * HE));
#pragma unroll
        for (int pi = 0; pi < 4; pi++) {
            uint4 q = pi == 0 ? q0 : pi == 1 ? q1 : pi == 2 ? q2 : q3;
            float we = pi == 0 ? w0 : pi == 1 ? w1 : pi == 2 ? w2 : w3;
            const __half2* hp = (const __half2*)&q;
            float2 f0 = __half22float2(hp[0]);
            float2 f1 = __half22float2(hp[1]);
            float2 f2 = __half22float2(hp[2]);
            float2 f3 = __half22float2(hp[3]);
            acc[0] = fmaf(we, f0.x, acc[0]); acc[1] = fmaf(we, f0.y, acc[1]);
            acc[2] = fmaf(we, f1.x, acc[2]); acc[3] = fmaf(we, f1.y, acc[3]);
            acc[4] = fmaf(we, f2.x, acc[4]); acc[5] = fmaf(we, f2.y, acc[5]);
            acc[6] = fmaf(we, f3.x, acc[6]); acc[7] = fmaf(we, f3.y, acc[7]);
        }
    }
    for (; e < deg && e < WCAP; e++) {
        int s = __shfl_sync(0xffffffffu, sreg[e >> 5], e & 31);
        float we = mysex[e * 4 + hh];
        uint4 q = __ldg((const uint4*)(xbase + (size_t)s * HE));
        const __half2* hp = (const __half2*)&q;
        float2 f0 = __half22float2(hp[0]);
        float2 f1 = __half22float2(hp[1]);
        float2 f2 = __half22float2(hp[2]);
        float2 f3 = __half22float2(hp[3]);
        acc[0] = fmaf(we, f0.x, acc[0]); acc[1] = fmaf(we, f0.y, acc[1]);
        acc[2] = fmaf(we, f1.x, acc[2]); acc[3] = fmaf(we, f1.y, acc[3]);
        acc[4] = fmaf(we, f2.x, acc[4]); acc[5] = fmaf(we, f2.y, acc[5]);
        acc[6] = fmaf(we, f3.x, acc[6]); acc[7] = fmaf(we, f3.y, acc[7]);
    }
    for (int ee = beg + WCAP; ee < end; ee++) {
        int s = g_permsrc[ee];
        float we = __ldg(&g_exbuf[(size_t)ee * 4 + hh]);
        uint4 q = __ldg((const uint4*)(xbase + (size_t)s * HE));
        const __half2* hp = (const __half2*)&q;
        float2 f0 = __half22float2(hp[0]);
        float2 f1 = __half22float2(hp[1]);
        float2 f2 = __half22float2(hp[2]);
        float2 f3 = __half22float2(hp[3]);
        acc[0] = fmaf(we, f0.x, acc[0]); acc[1] = fmaf(we, f0.y, acc[1]);
        acc[2] = fmaf(we, f1.x, acc[2]); acc[3] = fmaf(we, f1.y, acc[3]);
        acc[4] = fmaf(we, f2.x, acc[4]); acc[5] = fmaf(we, f2.y, acc[5]);
        acc[6] = fmaf(we, f3.x, acc[6]); acc[7] = fmaf(we, f3.y, acc[7]);
    }
    {
        uint4 q = __ldg((const uint4*)(xbase + (size_t)n * HE));
        const __half2* hp = (const __half2*)&q;
        float2 f0 = __half22float2(hp[0]);
        float2 f1 = __half22float2(hp[1]);
        float2 f2 = __half22float2(hp[2]);
        float2 f3 = __half22float2(hp[3]);
        acc[0] = fmaf(mylex, f0.x, acc[0]); acc[1] = fmaf(mylex, f0.y, acc[1]);
        acc[2] = fmaf(mylex, f1.x, acc[2]); acc[3] = fmaf(mylex, f1.y, acc[3]);
        acc[4] = fmaf(mylex, f2.x, acc[4]); acc[5] = fmaf(mylex, f2.y, acc[5]);
        acc[6] = fmaf(mylex, f3.x, acc[6]); acc[7] = fmaf(mylex, f3.y, acc[7]);
        const float4* bp = (const float4*)(gatb + col0);
        float4 b0 = __ldg(bp), b1 = __ldg(bp + 1);
        float o0 = fmaf(acc[0], myrc, b0.x), o1 = fmaf(acc[1], myrc, b0.y);
        float o2 = fmaf(acc[2], myrc, b0.z), o3 = fmaf(acc[3], myrc, b0.w);
        float o4 = fmaf(acc[4], myrc, b1.x), o5 = fmaf(acc[5], myrc, b1.y);
        float o6 = fmaf(acc[6], myrc, b1.z), o7 = fmaf(acc[7], myrc, b1.w);
        uint4 oq;
        __half2* oh = (__half2*)&oq;
        oh[0] = __float22half2_rn(make_float2(o0, o1));
        oh[1] = __float22half2_rn(make_float2(o2, o3));
        oh[2] = __float22half2_rn(make_float2(o4, o5));
        oh[3] = __float22half2_rn(make_float2(o6, o7));
        *(uint4*)(g_gout + (size_t)n * HE + col0) = oq;
    }
}

// ---------------- proj GEMM via wmma HMMA (fp16 A from g_gout, fp16 B in smem) -------
// + elu + residual + LN (+fused taskhead & copyout when last)
__global__ __launch_bounds__(256) void k_proj_ln(const float* __restrict__ B,
                                                 const float* __restrict__ pb,
                                                 const float* __restrict__ lg,
                                                 const float* __restrict__ lb,
                                                 int last,
                                                 const float* __restrict__ tW1,
                                                 const float* __restrict__ tb1,
                                                 const float* __restrict__ tW2,
                                                 const float* __restrict__ tb2,
                                                 float* __restrict__ out) {
    extern __shared__ float P[];
    float* As = P;                       // 8704 floats
    __half* Bh = (__half*)(P + 8704);    // 16384 halves = 8192 floats
    float* slg = P + 8704 + 8192;
    float* slb = slg + 64;
    float* spb = slb + 64;
    __shared__ float sW1[64 * 32];
    __shared__ float sW2[32];
    __shared__ float sb1[32];
    int tid = threadIdx.x;
    int wid = tid >> 5;
    int row0 = blockIdx.x * 128;
    if (tid < 64) { slg[tid] = __ldg(&lg[tid]); slb[tid] = __ldg(&lb[tid]); spb[tid] = __ldg(&pb[tid]); }
    if (last) {
        for (int i = tid; i < 64 * 32; i += 256) sW1[i] = tW1[i];
        if (tid < 32) { sW2[tid] = tW2[tid]; sb1[tid] = tb1[tid]; }
    }
    for (int i = tid; i < 256 * 64; i += 256) Bh[i] = __float2half(B[i]);
    __syncthreads();
    wmma::fragment<wmma::matrix_a, 16, 16, 16, __half, wmma::row_major> a_frag;
    wmma::fragment<wmma::matrix_b, 16, 16, 16, __half, wmma::row_major> b_frag;
    wmma::fragment<wmma::accumulator, 16, 16, 16, float> c_frag[4];
#pragma unroll
    for (int nf = 0; nf < 4; nf++) wmma::fill_fragment(c_frag[nf], 0.f);
    const __half* arow = g_gout + (size_t)(row0 + wid * 16) * HE;
#pragma unroll 4
    for (int k0 = 0; k0 < 256; k0 += 16) {
        wmma::load_matrix_sync(a_frag, arow + k0, HE);
#pragma unroll
        for (int nf = 0; nf < 4; nf++) {
            wmma::load_matrix_sync(b_frag, Bh + k0 * 64 + nf * 16, 64);
            wmma::mma_sync(c_frag[nf], a_frag, b_frag, c_frag[nf]);
        }
    }
#pragma unroll
    for (int nf = 0; nf < 4; nf++)
        wmma::store_matrix_sync(&As[wid * 16 * 68 + nf * 16], c_frag[nf], 68,
                                wmma::mem_row_major);
    __syncthreads();
    if (tid < 128) {
        int gr = row0 + tid;
        if (gr < NT) {
            float h[64];
            float s1 = 0.f, s2 = 0.f;
#pragma unroll
            for (int i = 0; i < 16; i++) {
                float4 a = *(float4*)&As[tid * 68 + i * 4];
                a.x += spb[i * 4];     a.x = (a.x > 0.f) ? a.x : (__expf(a.x) - 1.f);
                a.y += spb[i * 4 + 1]; a.y = (a.y > 0.f) ? a.y : (__expf(a.y) - 1.f);
                a.z += spb[i * 4 + 2]; a.z = (a.z > 0.f) ? a.z : (__expf(a.z) - 1.f);
                a.w += spb[i * 4 + 3]; a.w = (a.w > 0.f) ? a.w : (__expf(a.w) - 1.f);
                float4 b = *(const float4*)&g_ht[(size_t)gr * 64 + i * 4];
                float v0 = a.x + b.x, v1 = a.y + b.y, v2 = a.z + b.z, v3 = a.w + b.w;
                h[i * 4] = v0; h[i * 4 + 1] = v1; h[i * 4 + 2] = v2; h[i * 4 + 3] = v3;
                s1 += v0 + v1 + v2 + v3;
                s2 += v0 * v0 + v1 * v1 + v2 * v2 + v3 * v3;
            }
            float mu = s1 * (1.f / 64.f);
            float var = s2 * (1.f / 64.f) - mu * mu;
            float rs = rsqrtf(var + 1e-5f);
            const int OFF_HT = NT + NG;
#pragma unroll
            for (int i = 0; i < 16; i++) {
                float4 o;
                o.x = (h[i * 4] - mu) * rs * slg[i * 4] + slb[i * 4];
                o.y = (h[i * 4 + 1] - mu) * rs * slg[i * 4 + 1] + slb[i * 4 + 1];
                o.z = (h[i * 4 + 2] - mu) * rs * slg[i * 4 + 2] + slb[i * 4 + 2];
                o.w = (h[i * 4 + 3] - mu) * rs * slg[i * 4 + 3] + slb[i * 4 + 3];
                *(float4*)&g_ht[(size_t)gr * 64 + i * 4] = o;
                h[i * 4] = o.x; h[i * 4 + 1] = o.y; h[i * 4 + 2] = o.z; h[i * 4 + 3] = o.w;
                if (last) *(float4*)&out[OFF_HT + (size_t)gr * 64 + i * 4] = o;
            }
            if (last) {
                float logit = __ldg(tb2);
#pragma unroll
                for (int half = 0; half < 2; half++) {
                    float hid[16];
#pragma unroll
                    for (int j = 0; j < 16; j++) hid[j] = sb1[half * 16 + j];
#pragma unroll 4
                    for (int k = 0; k < 64; k++) {
                        float rv = h[k];
#pragma unroll
                        for (int j = 0; j < 16; j++)
                            hid[j] = fmaf(rv, sW1[k * 32 + half * 16 + j], hid[j]);
                    }
#pragma unroll
                    for (int j = 0; j < 16; j++)
                        logit = fmaf(fmaxf(hid[j], 0.f), sW2[half * 16 + j], logit);
                }
                out[gr] = logit;
            }
        }
    }
}

// ---------------- task pooling (128 rows/block) ----------------
__global__ void k_pool_task(const int* __restrict__ batch) {
    int c = threadIdx.x;
    int r0 = blockIdx.x * 128;
    int r1 = min(r0 + 128, NT);
    float acc = 0.f; int cg = -1; int cnt = 0;
    for (int r = r0; r < r1; r++) {
        int g = batch[r];
        if (g != cg) {
            if (cg >= 0) {
                atomicAdd(&g_tp[cg * 64 + c], acc);
                if (c == 0) atomicAdd(&g_cntt[cg], cnt);
            }
            cg = g; acc = 0.f; cnt = 0;
        }
        acc += g_ht[(size_t)r * 64 + c];
        cnt++;
    }
    if (cg >= 0) {
        atomicAdd(&g_tp[cg * 64 + c], acc);
        if (c == 0) atomicAdd(&g_cntt[cg], cnt);
    }
}

// ---------------- value head (inlines proc pooling + h_p copy-out; resets pool state) --
__global__ void k_value(const float* __restrict__ W1, const float* __restrict__ b1,
                        const float* __restrict__ W2, const float* __restrict__ b2,
                        const int* __restrict__ pbatch, float* __restrict__ out) {
    __shared__ float ge[NG * 128];
    __shared__ float red[512];
    __shared__ int sb[NP];
    int t = threadIdx.x;
    if (t < NP) sb[t] = pbatch[t];
    __syncthreads();
    const int OFF_HP = NT + NG + NT * EMB;
    for (int k = t; k < NP * EMB; k += 512) out[OFF_HP + k] = g_hp[k];
    for (int idx = t; idx < NG * 128; idx += 512) {
        int g = idx >> 7, k = idx & 127;
        float v;
        if (k < 64) {
            v = g_tp[g * 64 + k] / fmaxf((float)g_cntt[g], 1.f);
        } else {
            int j = k - 64;
            float s = 0.f; int cnt = 0;
            for (int r = 0; r < NP; r++) {
                if (sb[r] == g) { s += g_hp[r * 64 + j]; cnt++; }
            }
            v = s / fmaxf((float)cnt, 1.f);
        }
        ge[idx] = v;
    }
    __syncthreads();
    for (int idx = t; idx < NG * EMB; idx += 512) g_tp[idx] = 0.f;
    if (t < NG) g_cntt[t] = 0;
    int g = t >> 6, j = t & 63;
    float a = b1[j];
#pragma unroll 4
    for (int k = 0; k < 128; k++) a = fmaf(ge[g * 128 + k], W1[k * 64 + j], a);
    red[t] = fmaxf(a, 0.f) * W2[j];
    __syncthreads();
#pragma unroll
    for (int off = 32; off >= 1; off >>= 1) {
        if (j < off) red[t] += red[t + off];
        __syncthreads();
    }
    if (j == 0) out[NT + g] = red[t] + b2[0];
}

// ---------------- launch ----------------
extern "C" void kernel_launch(void* const* d_in, const int* in_sizes, int n_in,
                              void* d_out, int out_size) {
    const float *x_task, *x_proc, *edge_attr, *W_task, *b_task, *W_proc, *b_proc;
    const float *gat_W, *gat_We, *att_src, *att_dst, *att_edge, *gat_b, *proj_W, *proj_b;
    const float *ln_g, *ln_b, *pt_W1, *pt_b1, *pt_W2, *pt_b2, *v_W1, *v_b1, *v_W2, *v_b2;
    const int *edge_index, *task_batch, *proc_batch;

    if (in_sizes[2] == 2 * NE) {  // setup_inputs dict order
        x_task = (const float*)d_in[0];  x_proc = (const float*)d_in[1];
        edge_index = (const int*)d_in[2]; edge_attr = (const float*)d_in[3];
        task_batch = (const int*)d_in[4]; proc_batch = (const int*)d_in[5];
        W_task = (const float*)d_in[6];  b_task = (const float*)d_in[7];
        W_proc = (const float*)d_in[8];  b_proc = (const float*)d_in[9];
        gat_W = (const float*)d_in[10];  gat_We = (const float*)d_in[11];
        att_src = (const float*)d_in[12]; att_dst = (const float*)d_in[13];
        att_edge = (const float*)d_in[14]; gat_b = (const float*)d_in[15];
        proj_W = (const float*)d_in[16]; proj_b = (const float*)d_in[17];
        ln_g = (const float*)d_in[18];   ln_b = (const float*)d_in[19];
        pt_W1 = (const float*)d_in[20];  pt_b1 = (const float*)d_in[21];
        pt_W2 = (const float*)d_in[22];  pt_b2 = (const float*)d_in[23];
        v_W1 = (const float*)d_in[24];   v_b1 = (const float*)d_in[25];
        v_W2 = (const float*)d_in[26];   v_b2 = (const float*)d_in[27];
    } else {  // reference() signature order
        x_task = (const float*)d_in[0];  x_proc = (const float*)d_in[1];
        edge_attr = (const float*)d_in[2];
        W_task = (const float*)d_in[3];  b_task = (const float*)d_in[4];
        W_proc = (const float*)d_in[5];  b_proc = (const float*)d_in[6];
        gat_W = (const float*)d_in[7];   gat_We = (const float*)d_in[8];
        att_src = (const float*)d_in[9]; att_dst = (const float*)d_in[10];
        att_edge = (const float*)d_in[11]; gat_b = (const float*)d_in[12];
        proj_W = (const float*)d_in[13]; proj_b = (const float*)d_in[14];
        ln_g = (const float*)d_in[15];   ln_b = (const float*)d_in[16];
        pt_W1 = (const float*)d_in[17];  pt_b1 = (const float*)d_in[18];
        pt_W2 = (const float*)d_in[19];  pt_b2 = (const float*)d_in[20];
        v_W1 = (const float*)d_in[21];   v_b1 = (const float*)d_in[22];
        v_W2 = (const float*)d_in[23];   v_b2 = (const float*)d_in[24];
        edge_index = (const int*)d_in[25];
        task_batch = (const int*)d_in[26]; proc_batch = (const int*)d_in[27];
    }
    float* out = (float*)d_out;
    const int* e_src = edge_index;
    const int* e_dst = edge_index + NE;

    const int SMEM_G1 = 16896 * 4;
    const int SMEM_PJ = (8704 + 8192 + 192) * 4;   // As + Bh + slg/slb/spb
    cudaFuncSetAttribute(k_gemm1, cudaFuncAttributeMaxDynamicSharedMemorySize, SMEM_G1);
    cudaFuncSetAttribute(k_proj_ln, cudaFuncAttributeMaxDynamicSharedMemorySize, SMEM_PJ);

    cudaStream_t s2;
    cudaStreamCreateWithFlags(&s2, cudaStreamNonBlocking);
    cudaEvent_t evA, evB;
    cudaEventCreateWithFlags(&evA, cudaEventDisableTiming);
    cudaEventCreateWithFlags(&evB, cudaEventDisableTiming);

    k_setup<<<NT / 4 + 64 + 512, 256>>>(x_task, W_task, b_task, x_proc, W_proc, b_proc,
                                        edge_attr, e_dst);
    cudaEventRecord(evA, 0);
    cudaStreamWaitEvent(s2, evA, 0);
    k_gemm1<<<dim3((NT + 127) / 128, 2), 256, SMEM_G1, s2>>>(gat_W, att_src, att_dst);
    k_csr<<<SCAN_B, 256>>>(e_src, e_dst, edge_attr, gat_We, att_edge);
    cudaEventRecord(evB, s2);
    cudaStreamWaitEvent(0, evB, 0);

    for (int l = 0; l < NL; l++) {
        if (l > 0)
            k_gemm1<<<dim3((NT + 127) / 128, 2), 256, SMEM_G1>>>(
                gat_W + (size_t)l * EMB * HE, att_src + l * H * EMB, att_dst + l * H * EMB);
        k_agg<<<NT / 4, 128>>>(gat_b + l * HE, l);
        k_proj_ln<<<(NTP + 127) / 128, 256, SMEM_PJ>>>(
            proj_W + (size_t)l * HE * EMB, proj_b + l * EMB, ln_g + l * EMB, ln_b + l * EMB,
            (l == NL - 1) ? 1 : 0, pt_W1, pt_b1, pt_W2, pt_b2, out);
    }

    k_pool_task<<<(NT + 127) / 128, 64>>>(task_batch);
    k_value<<<1, 512>>>(v_W1, v_b1, v_W2, v_b2, proc_batch, out);

    cudaEventDestroy(evA);
    cudaEventDestroy(evB);
    cudaStreamDestroy(s2);
}

// round 16
// speedup vs baseline: 1.2137x; 1.0763x over previous
#include <cuda_runtime.h>
#include <cuda_fp16.h>
#include <mma.h>
#include <math.h>

using namespace nvcuda;

#define NT 50000
#define NTP 50048    // NT padded to 128 for wmma row tiles
#define NP 256
#define NE 800000
#define EMB 64
#define H 4
#define HE 256       // H*EMB
#define NL 3
#define EDIM 8
#define TDIM 16
#define PDIM 8
#define NG 8
#define SCAN_B 196   // ceil(NT/256)
#define WCAP 64      // per-warp smem edge stash (deg <= 64 fast path)

// ---------------- f32x2 packed-FMA helpers ----------------
union U2 { float4 f4; unsigned long long u[2]; };

__device__ __forceinline__ unsigned long long dup2(float x) {
    unsigned long long r;
    asm("mov.b64 %0, {%1, %1};" : "=l"(r) : "f"(x));
    return r;
}
__device__ __forceinline__ void ffma2(unsigned long long& d, unsigned long long a,
                                      unsigned long long b) {
    asm("fma.rn.f32x2 %0, %1, %2, %0;" : "+l"(d) : "l"(a), "l"(b));
}
__device__ __forceinline__ float2 unpack2(unsigned long long v) {
    float2 r;
    asm("mov.b64 {%0, %1}, %2;" : "=f"(r.x), "=f"(r.y) : "l"(v));
    return r;
}

// ---------------- scratch (static __device__, no allocs) ----------------
// state-recycling invariant: g_deg, g_meanea, g_tp, g_cntt, g_barcnt, g_donecnt
// are zero at entry (zero-init at load; reset by their consumers every run).
// g_gout rows [NT, NTP) stay zero forever (never written) -> safe wmma loads.
__device__ __half  g_xlh[(size_t)NT * HE];      // fp16 transformed feats (only copy)
__device__ __half  g_gout[(size_t)NTP * HE];    // fp16 GAT aggregation output (padded)
__device__ float   g_ht[(size_t)NT * EMB];
__device__ float   g_hp[NP * EMB];
__device__ float   g_asrc[NT * H];
__device__ float   g_adst[NT * H];
__device__ float   g_exbuf[(size_t)NE * H];     // overflow (deg > WCAP) ex only
__device__ __half  g_aedg[(size_t)NL * NE * H]; // per-edge per-layer attention dots (fp16)
__device__ int     g_permsrc[NE];
__device__ int     g_rowptr[NT + 1];
__device__ int     g_deg[NT];
__device__ int     g_off[NT];
__device__ int     g_bsum[SCAN_B];
__device__ float   g_meanea[EDIM];
__device__ float   g_c[NL * EDIM * H];
__device__ float   g_loopae[NL * H];
__device__ float   g_tp[NG * EMB];
__device__ int     g_cntt[NG];
__device__ int     g_barcnt;
__device__ int     g_donecnt;

// ---------------- fused setup: task embed + proc embed + meanea + dst hist ----------
__global__ void k_setup(const float* __restrict__ xt, const float* __restrict__ Wt,
                        const float* __restrict__ bt, const float* __restrict__ xp,
                        const float* __restrict__ Wp, const float* __restrict__ bp,
                        const float* __restrict__ ea, const int* __restrict__ dst) {
    int b = blockIdx.x;
    int tid = threadIdx.x;
    if (b < NT / 4) {
        __shared__ float sW[TDIM * EMB];
        __shared__ float sb[EMB];
        __shared__ float sx[4][TDIM];
        int tx = tid & 63, ty = tid >> 6;
        for (int i = tid; i < TDIM * EMB; i += 256) sW[i] = Wt[i];
        if (tid < EMB) sb[tid] = bt[tid];
        int n = b * 4 + ty;
        if (tx < TDIM) sx[ty][tx] = xt[(size_t)n * TDIM + tx];
        __syncthreads();
        float a = sb[tx];
#pragma unroll
        for (int k = 0; k < TDIM; k++) a = fmaf(sx[ty][k], sW[k * EMB + tx], a);
        g_ht[(size_t)n * EMB + tx] = a;
    } else if (b < NT / 4 + 64) {
        int idx = (b - NT / 4) * 256 + tid;
        int n = idx >> 6, c = idx & 63;
        float a = bp[c];
#pragma unroll
        for (int k = 0; k < PDIM; k++)
            a = fmaf(__ldg(&xp[n * PDIM + k]), __ldg(&Wp[k * EMB + c]), a);
        g_hp[idx] = a;
    } else {
        int i = (b - NT / 4 - 64) * 256 + tid;
        int stride = 512 * 256;
        float acc[8] = {0, 0, 0, 0, 0, 0, 0, 0};
        for (int e = i; e < NE; e += stride) {
            const float4* p = (const float4*)(ea + (size_t)e * 8);
            float4 a0 = p[0], a1 = p[1];
            acc[0] += a0.x; acc[1] += a0.y; acc[2] += a0.z; acc[3] += a0.w;
            acc[4] += a1.x; acc[5] += a1.y; acc[6] += a1.z; acc[7] += a1.w;
            atomicAdd(&g_deg[dst[e]], 1);
        }
#pragma unroll
        for (int k = 0; k < 8; k++)
#pragma unroll
            for (int off = 16; off >= 1; off >>= 1)
                acc[k] += __shfl_xor_sync(0xffffffffu, acc[k], off);
        if ((tid & 31) == 0)
#pragma unroll
            for (int k = 0; k < 8; k++) atomicAdd(&g_meanea[k], acc[k]);
    }
}

// ---------------- grid barrier (all 196 blocks co-resident; self-resetting) --------
__device__ __forceinline__ void gbar(int target) {
    __syncthreads();
    if (threadIdx.x == 0) {
        __threadfence();
        atomicAdd(&g_barcnt, 1);
        while (atomicAdd(&g_barcnt, 0) < target) { }
        __threadfence();
    }
    __syncthreads();
}

// ---------------- CSR build: scan + cvec + scatter(+aedg all layers, fp16) ----------
__global__ void k_csr(const int* __restrict__ src, const int* __restrict__ dst,
                      const float* __restrict__ ea, const float* __restrict__ We,
                      const float* __restrict__ ae) {
    int b = blockIdx.x, t = threadIdx.x;
    __shared__ int sm[256];
    __shared__ float scc[NL * 32];
    int idx = b * 256 + t;
    int v = (idx < NT) ? g_deg[idx] : 0;
    sm[t] = v;
    __syncthreads();
    for (int off = 1; off < 256; off <<= 1) {
        int u = (t >= off) ? sm[t - off] : 0;
        __syncthreads();
        sm[t] += u;
        __syncthreads();
    }
    if (idx < NT) g_rowptr[idx] = sm[t] - v;
    if (t == 255) g_bsum[b] = sm[255];
    gbar(SCAN_B);
    if (b == 0) {
        int w = (t < SCAN_B) ? g_bsum[t] : 0;
        sm[t] = w;
        __syncthreads();
        for (int off = 1; off < 256; off <<= 1) {
            int u = (t >= off) ? sm[t - off] : 0;
            __syncthreads();
            sm[t] += u;
            __syncthreads();
        }
        if (t < SCAN_B) g_bsum[t] = sm[t] - w;
    } else if (b == 1) {
        if (t < NL * EDIM * H) {
            int l = t >> 5; int r = t & 31; int j = r >> 2; int h = r & 3;
            float s = 0.f;
            for (int d = 0; d < EMB; d++)
                s += We[((size_t)(l * EDIM + j)) * HE + h * EMB + d] * ae[(l * H + h) * EMB + d];
            g_c[t] = s;
        }
        __syncthreads();
        if (t < NL * H) {
            int l = t >> 2; int h = t & 3;
            float s = 0.f;
            for (int j = 0; j < EDIM; j++)
                s += (g_meanea[j] * (1.f / NE)) * g_c[l * 32 + j * 4 + h];
            g_loopae[t] = s;
        }
        __syncthreads();
        if (t < EDIM) g_meanea[t] = 0.f;
    }
    gbar(2 * SCAN_B);
    if (idx < NT) {
        int r = g_rowptr[idx] + g_bsum[b];
        g_rowptr[idx] = r;
        g_off[idx] = r;
        g_deg[idx] = 0;
    }
    if (b == 0 && t == 0) g_rowptr[NT] = NE;
    gbar(3 * SCAN_B);
    if (t < NL * 32) scc[t] = g_c[t];
    __syncthreads();
    for (int e = b * 256 + t; e < NE; e += SCAN_B * 256) {
        int d = dst[e];
        int p = atomicAdd(&g_off[d], 1);
        g_permsrc[p] = src[e];
        const float4* sp = (const float4*)(ea + (size_t)e * 8);
        float4 a0 = sp[0], a1 = sp[1];
        float eav[8] = {a0.x, a0.y, a0.z, a0.w, a1.x, a1.y, a1.z, a1.w};
#pragma unroll
        for (int l = 0; l < NL; l++) {
            float o[4];
#pragma unroll
            for (int h = 0; h < 4; h++) {
                float s = 0.f;
#pragma unroll
                for (int j = 0; j < 8; j++) s = fmaf(eav[j], scc[l * 32 + j * 4 + h], s);
                o[h] = s;
            }
            uint2 oq;
            __half2* oh = (__half2*)&oq;
            oh[0] = __float22half2_rn(make_float2(o[0], o[1]));
            oh[1] = __float22half2_rn(make_float2(o[2], o[3]));
            *(uint2*)&g_aedg[(size_t)l * NE * 4 + (size_t)p * 4] = oq;
        }
    }
    __syncthreads();
    if (t == 0) {
        int old = atomicAdd(&g_donecnt, 1);
        if (old == SCAN_B - 1) {
            g_barcnt = 0;
            g_donecnt = 0;
            __threadfence();
        }
    }
}

// ---------------- GEMM1: xl = h_t @ W[l] (f32x2, 128x128 tile), fused att dots ----------
__global__ __launch_bounds__(256) void k_gemm1(const float* __restrict__ B,
                                               const float* __restrict__ as_,
                                               const float* __restrict__ ad_) {
    extern __shared__ float Q[];
    float* As = Q;
    float* Bs = Q + 8448;
    float* sas = Q + 16640;
    float* sad = Q + 16768;
    int tid = threadIdx.x;
    int row0 = blockIdx.x * 128;
    int col0 = blockIdx.y * 128;
#pragma unroll
    for (int i = 0; i < 32; i++) {
        int idx = tid + i * 256;
        int r = idx >> 6, k = idx & 63;
        int rr = row0 + r;
        As[k * 132 + r] = (rr < NT) ? g_ht[(size_t)rr * 64 + k] : 0.f;
    }
#pragma unroll
    for (int i = 0; i < 32; i++) {
        int idx = tid + i * 256;
        int k = idx >> 7, c = idx & 127;
        Bs[k * 128 + c] = B[(size_t)k * HE + col0 + c];
    }
    if (tid < 128) { sas[tid] = __ldg(&as_[col0 + tid]); sad[tid] = __ldg(&ad_[col0 + tid]); }
    __syncthreads();
    int tx = tid & 15, ty = tid >> 4;
    unsigned long long acc[4][8];
#pragma unroll
    for (int rp = 0; rp < 4; rp++)
#pragma unroll
        for (int c = 0; c < 8; c++) acc[rp][c] = 0ull;
#pragma unroll 4
    for (int k = 0; k < 64; k++) {
        U2 a0, a1;
        a0.f4 = *(const float4*)&As[k * 132 + ty * 4];
        a1.f4 = *(const float4*)&As[k * 132 + 64 + ty * 4];
        float4 b0 = *(const float4*)&Bs[k * 128 + tx * 4];
        float4 b1 = *(const float4*)&Bs[k * 128 + 64 + tx * 4];
        unsigned long long bd[8] = {dup2(b0.x), dup2(b0.y), dup2(b0.z), dup2(b0.w),
                                    dup2(b1.x), dup2(b1.y), dup2(b1.z), dup2(b1.w)};
        unsigned long long ap[4] = {a0.u[0], a0.u[1], a1.u[0], a1.u[1]};
#pragma unroll
        for (int rp = 0; rp < 4; rp++)
#pragma unroll
            for (int c = 0; c < 8; c++) ffma2(acc[rp][c], ap[rp], bd[c]);
    }
    int h0 = blockIdx.y * 2, h1 = h0 + 1;
#pragma unroll
    for (int rp = 0; rp < 4; rp++) {
        float2 u[8];
#pragma unroll
        for (int c = 0; c < 8; c++) u[c] = unpack2(acc[rp][c]);
        int rA = row0 + ((rp >> 1) ? 64 : 0) + ty * 4 + (rp & 1) * 2;
        if (rA < NT) {
            __half2* hp = (__half2*)&g_xlh[(size_t)rA * HE + col0 + tx * 4];
            hp[0] = __float22half2_rn(make_float2(u[0].x, u[1].x));
            hp[1] = __float22half2_rn(make_float2(u[2].x, u[3].x));
            __half2* hq = (__half2*)&g_xlh[(size_t)rA * HE + col0 + 64 + tx * 4];
            hq[0] = __float22half2_rn(make_float2(u[4].x, u[5].x));
            hq[1] = __float22half2_rn(make_float2(u[6].x, u[7].x));
        }
        if (rA + 1 < NT) {
            __half2* hp = (__half2*)&g_xlh[(size_t)(rA + 1) * HE + col0 + tx * 4];
            hp[0] = __float22half2_rn(make_float2(u[0].y, u[1].y));
            hp[1] = __float22half2_rn(make_float2(u[2].y, u[3].y));
            __half2* hq = (__half2*)&g_xlh[(size_t)(rA + 1) * HE + col0 + 64 + tx * 4];
            hq[0] = __float22half2_rn(make_float2(u[4].y, u[5].y));
            hq[1] = __float22half2_rn(make_float2(u[6].y, u[7].y));
        }
        float ps0 = 0, pd0 = 0, ps1 = 0, pd1 = 0, qs0 = 0, qd0 = 0, qs1 = 0, qd1 = 0;
#pragma unroll
        for (int j = 0; j < 4; j++) {
            float s0 = sas[tx * 4 + j], d0 = sad[tx * 4 + j];
            float s1 = sas[64 + tx * 4 + j], d1 = sad[64 + tx * 4 + j];
            ps0 = fmaf(u[j].x, s0, ps0); pd0 = fmaf(u[j].x, d0, pd0);
            qs0 = fmaf(u[j].y, s0, qs0); qd0 = fmaf(u[j].y, d0, qd0);
            ps1 = fmaf(u[4 + j].x, s1, ps1); pd1 = fmaf(u[4 + j].x, d1, pd1);
            qs1 = fmaf(u[4 + j].y, s1, qs1); qd1 = fmaf(u[4 + j].y, d1, qd1);
        }
#pragma unroll
        for (int off = 8; off >= 1; off >>= 1) {
            ps0 += __shfl_xor_sync(0xffffffffu, ps0, off);
            pd0 += __shfl_xor_sync(0xffffffffu, pd0, off);
            ps1 += __shfl_xor_sync(0xffffffffu, ps1, off);
            pd1 += __shfl_xor_sync(0xffffffffu, pd1, off);
            qs0 += __shfl_xor_sync(0xffffffffu, qs0, off);
            qd0 += __shfl_xor_sync(0xffffffffu, qd0, off);
            qs1 += __shfl_xor_sync(0xffffffffu, qs1, off);
            qd1 += __shfl_xor_sync(0xffffffffu, qd1, off);
        }
        if (tx == 0) {
            if (rA < NT) {
                g_asrc[rA * 4 + h0] = ps0; g_adst[rA * 4 + h0] = pd0;
                g_asrc[rA * 4 + h1] = ps1; g_adst[rA * 4 + h1] = pd1;
            }
            if (rA + 1 < NT) {
                g_asrc[(rA + 1) * 4 + h0] = qs0; g_adst[(rA + 1) * 4 + h0] = qd0;
                g_asrc[(rA + 1) * 4 + h1] = qs1; g_adst[(rA + 1) * 4 + h1] = qd1;
            }
        }
    }
}

// ---------------- attention + aggregate (warp/node; fp16 gather; fp16 gout) ----------
__global__ __launch_bounds__(128, 8) void k_agg(const float* __restrict__ gatb, int layer) {
    __shared__ float sex[4][WCAP * 4];
    int warp = blockIdx.x * 4 + (threadIdx.x >> 5);
    if (warp >= NT) return;
    int w = threadIdx.x >> 5;
    int lane = threadIdx.x & 31;
    int n = warp;
    const __half* aedg = g_aedg + (size_t)layer * NE * 4;
    int beg = g_rowptr[n], end = g_rowptr[n + 1];
    float4 t4 = *(const float4*)&g_adst[n * 4];
    float ad[4] = {t4.x, t4.y, t4.z, t4.w};
    t4 = *(const float4*)&g_asrc[n * 4];
    float lex[4], dn[4];
    {
        float an[4] = {t4.x, t4.y, t4.z, t4.w};
#pragma unroll
        for (int h = 0; h < 4; h++) {
            float v = an[h] + ad[h] + __ldg(&g_loopae[layer * 4 + h]);
            v = v > 0.f ? v : 0.2f * v;
            lex[h] = __expf(v);
            dn[h] = 0.f;
        }
    }
    int sreg[2] = {0, 0};
#pragma unroll
    for (int i = 0; i < 2; i++) {
        int e = beg + i * 32 + lane;
        if (e < end) {
            int s = g_permsrc[e];
            sreg[i] = s;
            float4 a4 = *(const float4*)&g_asrc[s * 4];
            uint2 q2 = __ldg((const uint2*)&aedg[(size_t)e * 4]);
            const __half2* h2 = (const __half2*)&q2;
            float2 g0 = __half22float2(h2[0]);
            float2 g1 = __half22float2(h2[1]);
            float as4[4] = {a4.x, a4.y, a4.z, a4.w};
            float ae4[4] = {g0.x, g0.y, g1.x, g1.y};
#pragma unroll
            for (int h = 0; h < 4; h++) {
                float v = as4[h] + ad[h] + ae4[h];
                v = v > 0.f ? v : 0.2f * v;
                float ex = __expf(v);
                sex[w][(i * 32 + lane) * 4 + h] = ex;
                dn[h] += ex;
            }
        }
    }
    for (int e = beg + WCAP + lane; e < end; e += 32) {
        int s = g_permsrc[e];
        float4 a4 = *(const float4*)&g_asrc[s * 4];
        uint2 q2 = __ldg((const uint2*)&aedg[(size_t)e * 4]);
        const __half2* h2 = (const __half2*)&q2;
        float2 g0 = __half22float2(h2[0]);
        float2 g1 = __half22float2(h2[1]);
        float as4[4] = {a4.x, a4.y, a4.z, a4.w};
        float ae4[4] = {g0.x, g0.y, g1.x, g1.y};
        float ex4[4];
#pragma unroll
        for (int h = 0; h < 4; h++) {
            float v = as4[h] + ad[h] + ae4[h];
            v = v > 0.f ? v : 0.2f * v;
            ex4[h] = __expf(v);
            dn[h] += ex4[h];
        }
        *(float4*)&g_exbuf[(size_t)e * 4] = make_float4(ex4[0], ex4[1], ex4[2], ex4[3]);
    }
#pragma unroll
    for (int off = 16; off >= 1; off >>= 1)
#pragma unroll
        for (int h = 0; h < 4; h++) dn[h] += __shfl_xor_sync(0xffffffffu, dn[h], off);
    int hh = lane >> 3;
    float myrc, mylex;
    {
        float rc[4];
#pragma unroll
        for (int h = 0; h < 4; h++) rc[h] = 1.f / (dn[h] + lex[h] + 1e-16f);
        myrc = hh == 0 ? rc[0] : hh == 1 ? rc[1] : hh == 2 ? rc[2] : rc[3];
        mylex = hh == 0 ? lex[0] : hh == 1 ? lex[1] : hh == 2 ? lex[2] : lex[3];
    }
    __syncwarp();
    int col0 = lane * 8;
    const __half* xbase = g_xlh + col0;
    float acc[8] = {0, 0, 0, 0, 0, 0, 0, 0};
    const float* mysex = sex[w];
    int deg = end - beg;
    int e = 0;
    for (; e + 4 <= deg && e + 4 <= WCAP; e += 4) {
        int s0 = __shfl_sync(0xffffffffu, sreg[e >> 5], e & 31);
        int s1 = __shfl_sync(0xffffffffu, sreg[(e + 1) >> 5], (e + 1) & 31);
        int s2 = __shfl_sync(0xffffffffu, sreg[(e + 2) >> 5], (e + 2) & 31);
        int s3 = __shfl_sync(0xffffffffu, sreg[(e + 3) >> 5], (e + 3) & 31);
        float w0 = mysex[e * 4 + hh];
        float w1 = mysex[(e + 1) * 4 + hh];
        float w2 = mysex[(e + 2) * 4 + hh];
        float w3 = mysex[(e + 3) * 4 + hh];
        uint4 q0 = __ldg((const uint4*)(xbase + (size_t)s0 * HE));
        uint4 q1 = __ldg((const uint4*)(xbase + (size_t)s1 * HE));
        uint4 q2 = __ldg((const uint4*)(xbase + (size_t)s2 * HE));
        uint4 q3 = __ldg((const uint4*)(xbase + (size_t)s3 * HE));
#pragma unroll
        for (int pi = 0; pi < 4; pi++) {
            uint4 q = pi == 0 ? q0 : pi == 1 ? q1 : pi == 2 ? q2 : q3;
            float we = pi == 0 ? w0 : pi == 1 ? w1 : pi == 2 ? w2 : w3;
            const __half2* hp = (const __half2*)&q;
            float2 f0 = __half22float2(hp[0]);
            float2 f1 = __half22float2(hp[1]);
            float2 f2 = __half22float2(hp[2]);
            float2 f3 = __half22float2(hp[3]);
            acc[0] = fmaf(we, f0.x, acc[0]); acc[1] = fmaf(we, f0.y, acc[1]);
            acc[2] = fmaf(we, f1.x, acc[2]); acc[3] = fmaf(we, f1.y, acc[3]);
            acc[4] = fmaf(we, f2.x, acc[4]); acc[5] = fmaf(we, f2.y, acc[5]);
            acc[6] = fmaf(we, f3.x, acc[6]); acc[7] = fmaf(we, f3.y, acc[7]);
        }
    }
    for (; e < deg && e < WCAP; e++) {
        int s = __shfl_sync(0xffffffffu, sreg[e >> 5], e & 31);
        float we = mysex[e * 4 + hh];
        uint4 q = __ldg((const uint4*)(xbase + (size_t)s * HE));
        const __half2* hp = (const __half2*)&q;
        float2 f0 = __half22float2(hp[0]);
        float2 f1 = __half22float2(hp[1]);
        float2 f2 = __half22float2(hp[2]);
        float2 f3 = __half22float2(hp[3]);
        acc[0] = fmaf(we, f0.x, acc[0]); acc[1] = fmaf(we, f0.y, acc[1]);
        acc[2] = fmaf(we, f1.x, acc[2]); acc[3] = fmaf(we, f1.y, acc[3]);
        acc[4] = fmaf(we, f2.x, acc[4]); acc[5] = fmaf(we, f2.y, acc[5]);
        acc[6] = fmaf(we, f3.x, acc[6]); acc[7] = fmaf(we, f3.y, acc[7]);
    }
    for (int ee = beg + WCAP; ee < end; ee++) {
        int s = g_permsrc[ee];
        float we = __ldg(&g_exbuf[(size_t)ee * 4 + hh]);
        uint4 q = __ldg((const uint4*)(xbase + (size_t)s * HE));
        const __half2* hp = (const __half2*)&q;
        float2 f0 = __half22float2(hp[0]);
        float2 f1 = __half22float2(hp[1]);
        float2 f2 = __half22float2(hp[2]);
        float2 f3 = __half22float2(hp[3]);
        acc[0] = fmaf(we, f0.x, acc[0]); acc[1] = fmaf(we, f0.y, acc[1]);
        acc[2] = fmaf(we, f1.x, acc[2]); acc[3] = fmaf(we, f1.y, acc[3]);
        acc[4] = fmaf(we, f2.x, acc[4]); acc[5] = fmaf(we, f2.y, acc[5]);
        acc[6] = fmaf(we, f3.x, acc[6]); acc[7] = fmaf(we, f3.y, acc[7]);
    }
    {
        uint4 q = __ldg((const uint4*)(xbase + (size_t)n * HE));
        const __half2* hp = (const __half2*)&q;
        float2 f0 = __half22float2(hp[0]);
        float2 f1 = __half22float2(hp[1]);
        float2 f2 = __half22float2(hp[2]);
        float2 f3 = __half22float2(hp[3]);
        acc[0] = fmaf(mylex, f0.x, acc[0]); acc[1] = fmaf(mylex, f0.y, acc[1]);
        acc[2] = fmaf(mylex, f1.x, acc[2]); acc[3] = fmaf(mylex, f1.y, acc[3]);
        acc[4] = fmaf(mylex, f2.x, acc[4]); acc[5] = fmaf(mylex, f2.y, acc[5]);
        acc[6] = fmaf(mylex, f3.x, acc[6]); acc[7] = fmaf(mylex, f3.y, acc[7]);
        const float4* bp = (const float4*)(gatb + col0);
        float4 b0 = __ldg(bp), b1 = __ldg(bp + 1);
        float o0 = fmaf(acc[0], myrc, b0.x), o1 = fmaf(acc[1], myrc, b0.y);
        float o2 = fmaf(acc[2], myrc, b0.z), o3 = fmaf(acc[3], myrc, b0.w);
        float o4 = fmaf(acc[4], myrc, b1.x), o5 = fmaf(acc[5], myrc, b1.y);
        float o6 = fmaf(acc[6], myrc, b1.z), o7 = fmaf(acc[7], myrc, b1.w);
        uint4 oq;
        __half2* oh = (__half2*)&oq;
        oh[0] = __float22half2_rn(make_float2(o0, o1));
        oh[1] = __float22half2_rn(make_float2(o2, o3));
        oh[2] = __float22half2_rn(make_float2(o4, o5));
        oh[3] = __float22half2_rn(make_float2(o6, o7));
        *(uint4*)(g_gout + (size_t)n * HE + col0) = oq;
    }
}

// ---------------- proj GEMM via wmma HMMA + elu + res + LN ---------------------------
// (+fused taskhead, h_t copyout, and task pooling when last)
__global__ __launch_bounds__(256) void k_proj_ln(const float* __restrict__ B,
                                                 const float* __restrict__ pb,
                                                 const float* __restrict__ lg,
                                                 const float* __restrict__ lb,
                                                 int last,
                                                 const float* __restrict__ tW1,
                                                 const float* __restrict__ tb1,
                                                 const float* __restrict__ tW2,
                                                 const float* __restrict__ tb2,
                                                 const int* __restrict__ batch,
                                                 float* __restrict__ out) {
    extern __shared__ float P[];
    float* As = P;                       // 8704 floats
    __half* Bh = (__half*)(P + 8704);    // 16384 halves = 8192 floats
    float* slg = P + 8704 + 8192;
    float* slb = slg + 64;
    float* spb = slb + 64;
    __shared__ float sW1[64 * 32];
    __shared__ float sW2[32];
    __shared__ float sb1[32];
    int tid = threadIdx.x;
    int wid = tid >> 5;
    int row0 = blockIdx.x * 128;
    if (tid < 64) { slg[tid] = __ldg(&lg[tid]); slb[tid] = __ldg(&lb[tid]); spb[tid] = __ldg(&pb[tid]); }
    if (last) {
        for (int i = tid; i < 64 * 32; i += 256) sW1[i] = tW1[i];
        if (tid < 32) { sW2[tid] = tW2[tid]; sb1[tid] = tb1[tid]; }
    }
    for (int i = tid; i < 256 * 64; i += 256) Bh[i] = __float2half(B[i]);
    __syncthreads();
    wmma::fragment<wmma::matrix_a, 16, 16, 16, __half, wmma::row_major> a_frag;
    wmma::fragment<wmma::matrix_b, 16, 16, 16, __half, wmma::row_major> b_frag;
    wmma::fragment<wmma::accumulator, 16, 16, 16, float> c_frag[4];
#pragma unroll
    for (int nf = 0; nf < 4; nf++) wmma::fill_fragment(c_frag[nf], 0.f);
    const __half* arow = g_gout + (size_t)(row0 + wid * 16) * HE;
#pragma unroll 4
    for (int k0 = 0; k0 < 256; k0 += 16) {
        wmma::load_matrix_sync(a_frag, arow + k0, HE);
#pragma unroll
        for (int nf = 0; nf < 4; nf++) {
            wmma::load_matrix_sync(b_frag, Bh + k0 * 64 + nf * 16, 64);
            wmma::mma_sync(c_frag[nf], a_frag, b_frag, c_frag[nf]);
        }
    }
#pragma unroll
    for (int nf = 0; nf < 4; nf++)
        wmma::store_matrix_sync(&As[wid * 16 * 68 + nf * 16], c_frag[nf], 68,
                                wmma::mem_row_major);
    __syncthreads();
    if (tid < 128) {
        int gr = row0 + tid;
        if (gr < NT) {
            float h[64];
            float s1 = 0.f, s2 = 0.f;
#pragma unroll
            for (int i = 0; i < 16; i++) {
                float4 a = *(float4*)&As[tid * 68 + i * 4];
                a.x += spb[i * 4];     a.x = (a.x > 0.f) ? a.x : (__expf(a.x) - 1.f);
                a.y += spb[i * 4 + 1]; a.y = (a.y > 0.f) ? a.y : (__expf(a.y) - 1.f);
                a.z += spb[i * 4 + 2]; a.z = (a.z > 0.f) ? a.z : (__expf(a.z) - 1.f);
                a.w += spb[i * 4 + 3]; a.w = (a.w > 0.f) ? a.w : (__expf(a.w) - 1.f);
                float4 b = *(const float4*)&g_ht[(size_t)gr * 64 + i * 4];
                float v0 = a.x + b.x, v1 = a.y + b.y, v2 = a.z + b.z, v3 = a.w + b.w;
                h[i * 4] = v0; h[i * 4 + 1] = v1; h[i * 4 + 2] = v2; h[i * 4 + 3] = v3;
                s1 += v0 + v1 + v2 + v3;
                s2 += v0 * v0 + v1 * v1 + v2 * v2 + v3 * v3;
            }
            float mu = s1 * (1.f / 64.f);
            float var = s2 * (1.f / 64.f) - mu * mu;
            float rs = rsqrtf(var + 1e-5f);
            const int OFF_HT = NT + NG;
#pragma unroll
            for (int i = 0; i < 16; i++) {
                float4 o;
                o.x = (h[i * 4] - mu) * rs * slg[i * 4] + slb[i * 4];
                o.y = (h[i * 4 + 1] - mu) * rs * slg[i * 4 + 1] + slb[i * 4 + 1];
                o.z = (h[i * 4 + 2] - mu) * rs * slg[i * 4 + 2] + slb[i * 4 + 2];
                o.w = (h[i * 4 + 3] - mu) * rs * slg[i * 4 + 3] + slb[i * 4 + 3];
                *(float4*)&g_ht[(size_t)gr * 64 + i * 4] = o;
                h[i * 4] = o.x; h[i * 4 + 1] = o.y; h[i * 4 + 2] = o.z; h[i * 4 + 3] = o.w;
                if (last) {
                    *(float4*)&out[OFF_HT + (size_t)gr * 64 + i * 4] = o;
                    *(float4*)&As[tid * 68 + i * 4] = o;   // stage for fused pooling
                }
            }
            if (last) {
                float logit = __ldg(tb2);
#pragma unroll
                for (int half = 0; half < 2; half++) {
                    float hid[16];
#pragma unroll
                    for (int j = 0; j < 16; j++) hid[j] = sb1[half * 16 + j];
#pragma unroll 4
                    for (int k = 0; k < 64; k++) {
                        float rv = h[k];
#pragma unroll
                        for (int j = 0; j < 16; j++)
                            hid[j] = fmaf(rv, sW1[k * 32 + half * 16 + j], hid[j]);
                    }
#pragma unroll
                    for (int j = 0; j < 16; j++)
                        logit = fmaf(fmaxf(hid[j], 0.f), sW2[half * 16 + j], logit);
                }
                out[gr] = logit;
            }
        }
    }
    // fused task pooling over this tile's rows (last layer only)
    if (last) {
        __syncthreads();
        int rmax = NT - row0;
        if (rmax > 128) rmax = 128;
        if (tid < 64 && rmax > 0) {
            int c = tid;
            float acc = 0.f; int cg = -1; int cnt = 0;
            for (int r = 0; r < rmax; r++) {
                int g = batch[row0 + r];
                if (g != cg) {
                    if (cg >= 0) {
                        atomicAdd(&g_tp[cg * 64 + c], acc);
                        if (c == 0) atomicAdd(&g_cntt[cg], cnt);
                    }
                    cg = g; acc = 0.f; cnt = 0;
                }
                acc += As[r * 68 + c];
                cnt++;
            }
            if (cg >= 0) {
                atomicAdd(&g_tp[cg * 64 + c], acc);
                if (c == 0) atomicAdd(&g_cntt[cg], cnt);
            }
        }
    }
}

// ---------------- value head (inlines proc pooling + h_p copy-out; resets pool state) --
__global__ void k_value(const float* __restrict__ W1, const float* __restrict__ b1,
                        const float* __restrict__ W2, const float* __restrict__ b2,
                        const int* __restrict__ pbatch, float* __restrict__ out) {
    __shared__ float ge[NG * 128];
    __shared__ float red[512];
    __shared__ int sb[NP];
    int t = threadIdx.x;
    if (t < NP) sb[t] = pbatch[t];
    __syncthreads();
    const int OFF_HP = NT + NG + NT * EMB;
    for (int k = t; k < NP * EMB; k += 512) out[OFF_HP + k] = g_hp[k];
    for (int idx = t; idx < NG * 128; idx += 512) {
        int g = idx >> 7, k = idx & 127;
        float v;
        if (k < 64) {
            v = g_tp[g * 64 + k] / fmaxf((float)g_cntt[g], 1.f);
        } else {
            int j = k - 64;
            float s = 0.f; int cnt = 0;
            for (int r = 0; r < NP; r++) {
                if (sb[r] == g) { s += g_hp[r * 64 + j]; cnt++; }
            }
            v = s / fmaxf((float)cnt, 1.f);
        }
        ge[idx] = v;
    }
    __syncthreads();
    for (int idx = t; idx < NG * EMB; idx += 512) g_tp[idx] = 0.f;
    if (t < NG) g_cntt[t] = 0;
    int g = t >> 6, j = t & 63;
    float a = b1[j];
#pragma unroll 4
    for (int k = 0; k < 128; k++) a = fmaf(ge[g * 128 + k], W1[k * 64 + j], a);
    red[t] = fmaxf(a, 0.f) * W2[j];
    __syncthreads();
#pragma unroll
    for (int off = 32; off >= 1; off >>= 1) {
        if (j < off) red[t] += red[t + off];
        __syncthreads();
    }
    if (j == 0) out[NT + g] = red[t] + b2[0];
}

// ---------------- launch ----------------
extern "C" void kernel_launch(void* const* d_in, const int* in_sizes, int n_in,
                              void* d_out, int out_size) {
    const float *x_task, *x_proc, *edge_attr, *W_task, *b_task, *W_proc, *b_proc;
    const float *gat_W, *gat_We, *att_src, *att_dst, *att_edge, *gat_b, *proj_W, *proj_b;
    const float *ln_g, *ln_b, *pt_W1, *pt_b1, *pt_W2, *pt_b2, *v_W1, *v_b1, *v_W2, *v_b2;
    const int *edge_index, *task_batch, *proc_batch;

    if (in_sizes[2] == 2 * NE) {  // setup_inputs dict order
        x_task = (const float*)d_in[0];  x_proc = (const float*)d_in[1];
        edge_index = (const int*)d_in[2]; edge_attr = (const float*)d_in[3];
        task_batch = (const int*)d_in[4]; proc_batch = (const int*)d_in[5];
        W_task = (const float*)d_in[6];  b_task = (const float*)d_in[7];
        W_proc = (const float*)d_in[8];  b_proc = (const float*)d_in[9];
        gat_W = (const float*)d_in[10];  gat_We = (const float*)d_in[11];
        att_src = (const float*)d_in[12]; att_dst = (const float*)d_in[13];
        att_edge = (const float*)d_in[14]; gat_b = (const float*)d_in[15];
        proj_W = (const float*)d_in[16]; proj_b = (const float*)d_in[17];
        ln_g = (const float*)d_in[18];   ln_b = (const float*)d_in[19];
        pt_W1 = (const float*)d_in[20];  pt_b1 = (const float*)d_in[21];
        pt_W2 = (const float*)d_in[22];  pt_b2 = (const float*)d_in[23];
        v_W1 = (const float*)d_in[24];   v_b1 = (const float*)d_in[25];
        v_W2 = (const float*)d_in[26];   v_b2 = (const float*)d_in[27];
    } else {  // reference() signature order
        x_task = (const float*)d_in[0];  x_proc = (const float*)d_in[1];
        edge_attr = (const float*)d_in[2];
        W_task = (const float*)d_in[3];  b_task = (const float*)d_in[4];
        W_proc = (const float*)d_in[5];  b_proc = (const float*)d_in[6];
        gat_W = (const float*)d_in[7];   gat_We = (const float*)d_in[8];
        att_src = (const float*)d_in[9]; att_dst = (const float*)d_in[10];
        att_edge = (const float*)d_in[11]; gat_b = (const float*)d_in[12];
        proj_W = (const float*)d_in[13]; proj_b = (const float*)d_in[14];
        ln_g = (const float*)d_in[15];   ln_b = (const float*)d_in[16];
        pt_W1 = (const float*)d_in[17];  pt_b1 = (const float*)d_in[18];
        pt_W2 = (const float*)d_in[19];  pt_b2 = (const float*)d_in[20];
        v_W1 = (const float*)d_in[21];   v_b1 = (const float*)d_in[22];
        v_W2 = (const float*)d_in[23];   v_b2 = (const float*)d_in[24];
        edge_index = (const int*)d_in[25];
        task_batch = (const int*)d_in[26]; proc_batch = (const int*)d_in[27];
    }
    float* out = (float*)d_out;
    const int* e_src = edge_index;
    const int* e_dst = edge_index + NE;

    const int SMEM_G1 = 16896 * 4;
    const int SMEM_PJ = (8704 + 8192 + 192) * 4;   // As + Bh + slg/slb/spb
    cudaFuncSetAttribute(k_gemm1, cudaFuncAttributeMaxDynamicSharedMemorySize, SMEM_G1);
    cudaFuncSetAttribute(k_proj_ln, cudaFuncAttributeMaxDynamicSharedMemorySize, SMEM_PJ);

    cudaStream_t s2;
    cudaStreamCreateWithFlags(&s2, cudaStreamNonBlocking);
    cudaEvent_t evA, evB;
    cudaEventCreateWithFlags(&evA, cudaEventDisableTiming);
    cudaEventCreateWithFlags(&evB, cudaEventDisableTiming);

    k_setup<<<NT / 4 + 64 + 512, 256>>>(x_task, W_task, b_task, x_proc, W_proc, b_proc,
                                        edge_attr, e_dst);
    cudaEventRecord(evA, 0);
    cudaStreamWaitEvent(s2, evA, 0);
    k_gemm1<<<dim3((NT + 127) / 128, 2), 256, SMEM_G1, s2>>>(gat_W, att_src, att_dst);
    k_csr<<<SCAN_B, 256>>>(e_src, e_dst, edge_attr, gat_We, att_edge);
    cudaEventRecord(evB, s2);
    cudaStreamWaitEvent(0, evB, 0);

    for (int l = 0; l < NL; l++) {
        if (l > 0)
            k_gemm1<<<dim3((NT + 127) / 128, 2), 256, SMEM_G1>>>(
                gat_W + (size_t)l * EMB * HE, att_src + l * H * EMB, att_dst + l * H * EMB);
        k_agg<<<NT / 4, 128>>>(gat_b + l * HE, l);
        k_proj_ln<<<(NTP + 127) / 128, 256, SMEM_PJ>>>(
            proj_W + (size_t)l * HE * EMB, proj_b + l * EMB, ln_g + l * EMB, ln_b + l * EMB,
            (l == NL - 1) ? 1 : 0, pt_W1, pt_b1, pt_W2, pt_b2, task_batch, out);
    }

    k_value<<<1, 512>>>(v_W1, v_b1, v_W2, v_b2, proc_batch, out);

    cudaEventDestroy(evA);
    cudaEventDestroy(evB);
    cudaStreamDestroy(s2);
}